// round 3
// baseline (speedup 1.0000x reference)
#include <cuda_runtime.h>
#include <math.h>

#define FULLMASK 0xffffffffu
#define TWO_PI_F 6.2831853071795864f

// ---------------- scratch ----------------
__device__ float g_ts[256 * 256];   // ts angles, row b: [s*64 + g]

// ---------------- sim14 single-layer op schedule (32 ops) ----------------
__device__ constexpr int OPC[32] = {
    -1,-1,-1,-1,-1,-1,-1,-1,
     7, 6, 5, 4, 3, 2, 1, 0,
    -1,-1,-1,-1,-1,-1,-1,-1,
     7, 0, 1, 2, 3, 4, 5, 6};
__device__ constexpr int OPT[32] = {
     0, 1, 2, 3, 4, 5, 6, 7,
     0, 7, 6, 5, 4, 3, 2, 1,
     0, 1, 2, 3, 4, 5, 6, 7,
     6, 7, 0, 1, 2, 3, 4, 5};

// ---------------- helpers ----------------
__device__ __forceinline__ float g4(float4 v, int i) {
    return (i == 0) ? v.x : (i == 1) ? v.y : (i == 2) ? v.z : v.w;
}
__device__ __forceinline__ float4 splat4(float v) { return make_float4(v, v, v, v); }

// State layout (4 warps per batch element, 128 threads):
//   flat index n (10 bits): bit9..bit5 = wires 0..4 (lane bits 4..0),
//   bit4 = wire5 (tid bit 6), bit3 = wire6 (tid bit 5),
//   bit2 = wire7 (reg bit 2), bit1 = wire8/anc0, bit0 = wire9/anc1.
//   Each thread holds 8 float2 (r = bits 2..0). select index s = r & 3.
#define OIDX(n) ((n) ^ (((n) >> 5) & 31))

// RY on a lane-bit wire
__device__ __forceinline__ void ry_lane(float2 (&st)[8], int lmask, int lb, int lane,
                                        float4 c, float4 s) {
    float sg = ((lane >> lb) & 1) ? 1.f : -1.f;
    float4 sv = make_float4(g4(s,0)*sg, g4(s,1)*sg, g4(s,2)*sg, g4(s,3)*sg);
#pragma unroll
    for (int r = 0; r < 8; ++r) {
        float ox = __shfl_xor_sync(FULLMASK, st[r].x, lmask);
        float oy = __shfl_xor_sync(FULLMASK, st[r].y, lmask);
        float pc = g4(c, r & 3), ps = g4(sv, r & 3);
        st[r].x = fmaf(pc, st[r].x, ps * ox);
        st[r].y = fmaf(pc, st[r].y, ps * oy);
    }
}

// RY on a reg-bit wire (mask M in {4,2,1})
template <int M>
__device__ __forceinline__ void ry_reg(float2 (&st)[8], float4 c, float4 s) {
#pragma unroll
    for (int r = 0; r < 8; ++r) {
        if ((r & M) == 0) {
            const int r1 = r | M;
            float pc = g4(c, r & 3), ps = g4(s, r & 3);
            float ax = st[r].x, ay = st[r].y, bx = st[r1].x, by = st[r1].y;
            st[r].x = fmaf(pc, ax, -ps * bx);
            st[r].y = fmaf(pc, ay, -ps * by);
            st[r1].x = fmaf(ps, ax, pc * bx);
            st[r1].y = fmaf(ps, ay, pc * by);
        }
    }
}

// CRX with target on a lane-bit wire
__device__ __forceinline__ void crx_lane(float2 (&st)[8], int tmask,
                                         bool actBase, int crm, float4 c, float4 s) {
#pragma unroll
    for (int r = 0; r < 8; ++r) {
        float ox = __shfl_xor_sync(FULLMASK, st[r].x, tmask);
        float oy = __shfl_xor_sync(FULLMASK, st[r].y, tmask);
        bool act = actBase && (crm == 0 || (r & crm) != 0);
        float pc = g4(c, r & 3), ps = g4(s, r & 3);
        float nx = fmaf(pc, st[r].x, ps * oy);
        float ny = fmaf(pc, st[r].y, -ps * ox);
        if (act) { st[r].x = nx; st[r].y = ny; }
    }
}

// CRX with target on a reg-bit wire (mask M)
template <int M>
__device__ __forceinline__ void crx_reg(float2 (&st)[8], bool actBase, int crm,
                                        float4 c, float4 s) {
#pragma unroll
    for (int r = 0; r < 8; ++r) {
        if ((r & M) == 0) {
            const int r1 = r | M;
            bool act = actBase && (crm == 0 || (r & crm) != 0);
            float pc = g4(c, r & 3), ps = g4(s, r & 3);
            float ax = st[r].x, ay = st[r].y, bx = st[r1].x, by = st[r1].y;
            float n0x = fmaf(pc, ax, ps * by);
            float n0y = fmaf(pc, ay, -ps * bx);
            float n1x = fmaf(pc, bx, ps * ay);
            float n1y = fmaf(pc, by, -ps * ax);
            if (act) { st[r] = make_float2(n0x, n0y); st[r1] = make_float2(n1x, n1y); }
        }
    }
}

// Op (RY or CRX) whose target is a warp bit: smem exchange. xm = 64 (w5) or 32 (w6)
__device__ __forceinline__ void warp_op(float2 (&st)[8], float2* sbuf,
                                        int tid, int xm, bool isRY,
                                        bool actBase, int crm, float4 c, float4 s) {
    __syncthreads();
#pragma unroll
    for (int r = 0; r < 8; ++r) sbuf[r * 128 + tid] = st[r];
    __syncthreads();
    const int p = tid ^ xm;
    const float sg = (tid & xm) ? 1.f : -1.f;
#pragma unroll
    for (int r = 0; r < 8; ++r) {
        float2 o = sbuf[r * 128 + p];
        float pc = g4(c, r & 3), ps = g4(s, r & 3);
        if (isRY) {
            st[r].x = fmaf(pc, st[r].x, sg * ps * o.x);
            st[r].y = fmaf(pc, st[r].y, sg * ps * o.y);
        } else {
            bool act = actBase && (crm == 0 || (r & crm) != 0);
            float nx = fmaf(pc, st[r].x, ps * o.y);
            float ny = fmaf(pc, st[r].y, -ps * o.x);
            if (act) { st[r].x = nx; st[r].y = ny; }
        }
    }
}

// RZ on a reg-bit wire (ancilla)
template <int M>
__device__ __forceinline__ void rz_reg(float2 (&st)[8], float c, float s) {
#pragma unroll
    for (int r = 0; r < 8; ++r) {
        float ss = (r & M) ? s : -s;
        float x = st[r].x, y = st[r].y;
        st[r].x = fmaf(c, x, -ss * y);
        st[r].y = fmaf(c, y, ss * x);
    }
}

__device__ __forceinline__ void cnot_st(float2 (&st)[8]) {
#pragma unroll
    for (int r = 0; r < 8; ++r) {
        if ((r & 3) == 2) { float2 tmp = st[r]; st[r] = st[r | 1]; st[r | 1] = tmp; }
    }
}

__device__ __forceinline__ void pcphase_g(float2 (&st)[8], float cphi, float sphi) {
#pragma unroll
    for (int r = 0; r < 8; ++r) {
        float ss = ((r & 3) == 0) ? sphi : -sphi;
        float x = st[r].x, y = st[r].y;
        st[r].x = fmaf(cphi, x, -ss * y);
        st[r].y = fmaf(cphi, y, ss * x);
    }
}

__device__ __forceinline__ void apply_op(float2 (&st)[8], int lane, int tid,
                                         float2* sbuf, int cw, int tw,
                                         float4 c, float4 s) {
    if (cw < 0) {  // RY
        if (tw < 5)       ry_lane(st, 1 << (4 - tw), 4 - tw, lane, c, s);
        else if (tw == 5) warp_op(st, sbuf, tid, 64, true, true, 0, c, s);
        else if (tw == 6) warp_op(st, sbuf, tid, 32, true, true, 0, c, s);
        else              ry_reg<4>(st, c, s);
    } else {       // CRX
        bool actBase; int crm = 0;
        if (cw < 5)       actBase = ((lane >> (4 - cw)) & 1) != 0;
        else if (cw == 5) actBase = ((tid >> 6) & 1) != 0;
        else if (cw == 6) actBase = ((tid >> 5) & 1) != 0;
        else { actBase = true; crm = 4; }
        if (tw < 5)       crx_lane(st, 1 << (4 - tw), actBase, crm, c, s);
        else if (tw == 5) warp_op(st, sbuf, tid, 64, false, actBase, crm, c, s);
        else if (tw == 6) warp_op(st, sbuf, tid, 32, false, actBase, crm, c, s);
        else              crx_reg<4>(st, actBase, crm, c, s);
    }
}

// 2-layer sim14 fully unrolled (compile-time op dispatch)
template <bool ADJ>
__device__ __forceinline__ void run_sim2l(float2 (&st)[8], int lane, int tid,
                                          float2* sbuf,
                                          const float4* tabc, const float4* tabs) {
#pragma unroll
    for (int u = 0; u < 64; ++u) {
        const int step = ADJ ? (63 - u) : u;
        const int o = step & 31;
        float4 c = tabc[step];
        float4 s0 = tabs[step];
        float4 s = ADJ ? make_float4(-s0.x, -s0.y, -s0.z, -s0.w) : s0;
        apply_op(st, lane, tid, sbuf, OPC[o], OPT[o], c, s);
    }
}

__device__ __forceinline__ void do_prepare(float2 (&st)[8], const float2* tabp, bool adj) {
    if (!adj) {
#pragma unroll
        for (int ly = 0; ly < 2; ++ly) {
            float2 a  = tabp[ly*4+0]; ry_reg<2>(st, splat4(a.x),  splat4(a.y));
            float2 z  = tabp[ly*4+1]; rz_reg<2>(st, z.x, z.y);
            float2 a2 = tabp[ly*4+2]; ry_reg<1>(st, splat4(a2.x), splat4(a2.y));
            float2 z2 = tabp[ly*4+3]; rz_reg<1>(st, z2.x, z2.y);
            cnot_st(st);
        }
    } else {
#pragma unroll
        for (int ly = 1; ly >= 0; --ly) {
            cnot_st(st);
            float2 z2 = tabp[ly*4+3]; rz_reg<1>(st, z2.x, -z2.y);
            float2 a2 = tabp[ly*4+2]; ry_reg<1>(st, splat4(a2.x), splat4(-a2.y));
            float2 z  = tabp[ly*4+1]; rz_reg<2>(st, z.x, -z.y);
            float2 a  = tabp[ly*4+0]; ry_reg<2>(st, splat4(a.x),  splat4(-a.y));
        }
    }
}

// ---------------- simulate kernel: 4 warps per batch element ----------------
__global__ void __launch_bounds__(128) k_sim(
    const float* __restrict__ prep_p, const float* __restrict__ sig,
    const float* __restrict__ qff,
    const float* __restrict__ A_obs, const float* __restrict__ B_obs,
    const float* __restrict__ D_obs,
    const float* __restrict__ head_w, const float* __restrict__ head_b,
    float* __restrict__ out) {
    __shared__ float2 sbuf[1024];
    __shared__ float4 tabc[64];
    __shared__ float4 tabs[64];
    __shared__ float2 tabq[32];
    __shared__ float2 tabp[8];
    __shared__ float2 tabsig[4];
    __shared__ float part[28];

    const int tid  = threadIdx.x;
    const int lane = tid & 31;
    const int warp = tid >> 5;
    const int b    = blockIdx.x;
    const float* tsr = g_ts + b * 256;

    if (tid < 64) {
        float c0,s0,c1,s1,c2,s2,c3,s3;
        sincosf(tsr[tid]       * 0.5f, &s0, &c0);
        sincosf(tsr[64 + tid]  * 0.5f, &s1, &c1);
        sincosf(tsr[128 + tid] * 0.5f, &s2, &c2);
        sincosf(tsr[192 + tid] * 0.5f, &s3, &c3);
        tabc[tid] = make_float4(c0, c1, c2, c3);
        tabs[tid] = make_float4(s0, s1, s2, s3);
    } else if (tid < 96) {
        int q = tid - 64;
        float sn, cc; sincosf(qff[q] * 0.5f, &sn, &cc);
        tabq[q] = make_float2(cc, sn);
    } else if (tid < 104) {
        int q = tid - 96;
        float sn, cc; sincosf(prep_p[q] * 0.5f, &sn, &cc);
        tabp[q] = make_float2(cc, sn);
    } else if (tid < 108) {
        int q = tid - 104;
        float sn, cc; sincosf(sig[q], &sn, &cc);
        tabsig[q] = make_float2(cc, sn);
    }
    __syncthreads();

    float2 st[8];
#pragma unroll
    for (int r = 0; r < 8; ++r) st[r] = make_float2(0.f, 0.f);
    if (tid == 0) st[0].x = 1.f;

    { float2 p = tabsig[0]; pcphase_g(st, p.x, p.y); }
#pragma unroll 1
    for (int k = 0; k < 3; ++k) {
        do_prepare(st, tabp, false);
        if ((k & 1) == 0) run_sim2l<false>(st, lane, tid, sbuf, tabc, tabs);
        else              run_sim2l<true>(st, lane, tid, sbuf, tabc, tabs);
        do_prepare(st, tabp, true);
        float2 p = tabsig[k + 1];
        pcphase_g(st, p.x, p.y);
    }
    // final sim14 with qff params, 1 layer (uniform theta)
#pragma unroll
    for (int step = 0; step < 32; ++step) {
        float2 tq = tabq[step];
        apply_op(st, lane, tid, sbuf, OPC[step], OPT[step],
                 splat4(tq.x), splat4(tq.y));
    }

    // dump state to shared (swizzled) for expectation values
    __syncthreads();
#pragma unroll
    for (int r = 0; r < 8; ++r) {
        int n = (lane << 5) | (warp << 3) | r;
        sbuf[OIDX(n)] = st[r];
    }
    __syncthreads();

#pragma unroll 1
    for (int w = 0; w < 7; ++w) {
        const float* Aw = A_obs + w * 6;
        const float* Bw = B_obs + w * 6;
        const float* Dw = D_obs + w * 4;
        float d0 = 2.f * Dw[1], d1 = 2.f * Dw[2], d2 = 2.f * Dw[3];
        float a10 = Aw[0], b10 = Bw[0], a20 = Aw[1], b20 = Bw[1], a21 = Aw[2], b21 = Bw[2];
        float a30 = Aw[3], b30 = Bw[3], a31 = Aw[4], b31 = Bw[4], a32 = Aw[5], b32 = Bw[5];
        int b1 = 8 - w;
        int m1 = 1 << b1, m0 = m1 << 1;
        int lowmask = m1 - 1;
        float acc = 0.f;
#pragma unroll
        for (int it = 0; it < 2; ++it) {
            int gi = tid + it * 128;
            int n = ((gi & ~lowmask) << 2) | (gi & lowmask);
            float2 v0 = sbuf[OIDX(n)];
            float2 v1 = sbuf[OIDX(n + m1)];
            float2 v2 = sbuf[OIDX(n + m0)];
            float2 v3 = sbuf[OIDX(n + m0 + m1)];
            acc += d0 * (v0.x * v0.x + v0.y * v0.y);
            acc += d1 * (v1.x * v1.x + v1.y * v1.y);
            acc += d2 * (v2.x * v2.x + v2.y * v2.y);
#define CROSS(vi, vj, aa, bb) { \
            float pr = vi.x * vj.x + vi.y * vj.y; \
            float pim = vi.x * vj.y - vi.y * vj.x; \
            acc += 2.f * (pr * (aa) - pim * (bb)); }
            CROSS(v1, v0, a10, b10)
            CROSS(v2, v0, a20, b20)
            CROSS(v2, v1, a21, b21)
            CROSS(v3, v0, a30, b30)
            CROSS(v3, v1, a31, b31)
            CROSS(v3, v2, a32, b32)
#undef CROSS
        }
#pragma unroll
        for (int off = 16; off; off >>= 1) acc += __shfl_xor_sync(FULLMASK, acc, off);
        if (lane == 0) part[w * 4 + warp] = acc;
    }
    __syncthreads();

    // head: out[b][j] = sum_w e[w] * head_w[j*7+w] + head_b[j]
    {
        int j = tid;
        float o = head_b[j];
#pragma unroll
        for (int w = 0; w < 7; ++w) {
            float e = part[w*4] + part[w*4+1] + part[w*4+2] + part[w*4+3];
            o = fmaf(e, head_w[j * 7 + w], o);
        }
        out[b * 128 + j] = o;
    }
}

// ---------------- fused MLP kernel: 4 batch rows per block ----------------
__device__ __forceinline__ float silu_f(float x) { return x * (1.f / (1.f + expf(-x))); }

__global__ void __launch_bounds__(256) k_mlp(
    const float* __restrict__ t, const float* __restrict__ z_t,
    const float* __restrict__ te_w1, const float* __restrict__ te_b1,
    const float* __restrict__ te_w2, const float* __restrict__ te_b2,
    const float* __restrict__ ip_w1, const float* __restrict__ ip_b1,
    const float* __restrict__ ip_w2, const float* __restrict__ ip_b2) {
    __shared__ float emb[4][128];
    __shared__ float hb[4][128];
    __shared__ float cat[4][256];
    __shared__ float g1[4][256];
    const int tid = threadIdx.x;
    const int r0 = blockIdx.x * 4;

    // stage A: sinusoidal embedding + copy z_t into cat
#pragma unroll
    for (int idx = tid; idx < 512; idx += 256) {
        int row = idx >> 7, i = idx & 127;
        float tv = t[r0 + row];
        int ii = i & 63;
        float f = expf(-0.14391156831212787f * (float)ii);
        float a = tv * f;
        emb[row][i] = (i < 64) ? cosf(a) : sinf(a);
        cat[row][i] = z_t[(r0 + row) * 128 + i];
    }
    __syncthreads();

    // stage B: h = silu(te_w1 @ emb + te_b1)
    if (tid < 128) {
        int j = tid;
        float acc[4];
        float bj = te_b1[j];
#pragma unroll
        for (int r = 0; r < 4; ++r) acc[r] = bj;
        const float4* w4 = reinterpret_cast<const float4*>(te_w1 + j * 128);
#pragma unroll 8
        for (int k4 = 0; k4 < 32; ++k4) {
            float4 wv = w4[k4];
#pragma unroll
            for (int r = 0; r < 4; ++r) {
                float4 x = *reinterpret_cast<const float4*>(&emb[r][k4 * 4]);
                acc[r] = fmaf(wv.x, x.x, acc[r]); acc[r] = fmaf(wv.y, x.y, acc[r]);
                acc[r] = fmaf(wv.z, x.z, acc[r]); acc[r] = fmaf(wv.w, x.w, acc[r]);
            }
        }
#pragma unroll
        for (int r = 0; r < 4; ++r) hb[r][j] = silu_f(acc[r]);
    }
    __syncthreads();

    // stage C: t_emb2 = te_w2 @ h + te_b2 -> cat[., 128+j]
    if (tid < 128) {
        int j = tid;
        float acc[4];
        float bj = te_b2[j];
#pragma unroll
        for (int r = 0; r < 4; ++r) acc[r] = bj;
        const float4* w4 = reinterpret_cast<const float4*>(te_w2 + j * 128);
#pragma unroll 8
        for (int k4 = 0; k4 < 32; ++k4) {
            float4 wv = w4[k4];
#pragma unroll
            for (int r = 0; r < 4; ++r) {
                float4 x = *reinterpret_cast<const float4*>(&hb[r][k4 * 4]);
                acc[r] = fmaf(wv.x, x.x, acc[r]); acc[r] = fmaf(wv.y, x.y, acc[r]);
                acc[r] = fmaf(wv.z, x.z, acc[r]); acc[r] = fmaf(wv.w, x.w, acc[r]);
            }
        }
#pragma unroll
        for (int r = 0; r < 4; ++r) cat[r][128 + j] = acc[r];
    }
    __syncthreads();

    // stage D: g1 = silu(ip_w1 @ cat + ip_b1)
    {
        int j = tid;
        float acc[4];
        float bj = ip_b1[j];
#pragma unroll
        for (int r = 0; r < 4; ++r) acc[r] = bj;
        const float4* w4 = reinterpret_cast<const float4*>(ip_w1 + j * 256);
#pragma unroll 8
        for (int k4 = 0; k4 < 64; ++k4) {
            float4 wv = w4[k4];
#pragma unroll
            for (int r = 0; r < 4; ++r) {
                float4 x = *reinterpret_cast<const float4*>(&cat[r][k4 * 4]);
                acc[r] = fmaf(wv.x, x.x, acc[r]); acc[r] = fmaf(wv.y, x.y, acc[r]);
                acc[r] = fmaf(wv.z, x.z, acc[r]); acc[r] = fmaf(wv.w, x.w, acc[r]);
            }
        }
#pragma unroll
        for (int r = 0; r < 4; ++r) g1[r][j] = silu_f(acc[r]);
    }
    __syncthreads();

    // stage E: ts = sigmoid(ip_w2 @ g1 + ip_b2) * 2pi
    {
        int j = tid;
        float acc[4];
        float bj = ip_b2[j];
#pragma unroll
        for (int r = 0; r < 4; ++r) acc[r] = bj;
        const float4* w4 = reinterpret_cast<const float4*>(ip_w2 + j * 256);
#pragma unroll 8
        for (int k4 = 0; k4 < 64; ++k4) {
            float4 wv = w4[k4];
#pragma unroll
            for (int r = 0; r < 4; ++r) {
                float4 x = *reinterpret_cast<const float4*>(&g1[r][k4 * 4]);
                acc[r] = fmaf(wv.x, x.x, acc[r]); acc[r] = fmaf(wv.y, x.y, acc[r]);
                acc[r] = fmaf(wv.z, x.z, acc[r]); acc[r] = fmaf(wv.w, x.w, acc[r]);
            }
        }
#pragma unroll
        for (int r = 0; r < 4; ++r)
            g_ts[(r0 + r) * 256 + j] = TWO_PI_F / (1.f + expf(-acc[r]));
    }
}

// ---------------- launch ----------------
extern "C" void kernel_launch(void* const* d_in, const int* in_sizes, int n_in,
                              void* d_out, int out_size) {
    const float* z_t    = (const float*)d_in[0];
    const float* t      = (const float*)d_in[1];
    const float* te_w1  = (const float*)d_in[2];
    const float* te_b1  = (const float*)d_in[3];
    const float* te_w2  = (const float*)d_in[4];
    const float* te_b2  = (const float*)d_in[5];
    const float* ip_w1  = (const float*)d_in[6];
    const float* ip_b1  = (const float*)d_in[7];
    const float* ip_w2  = (const float*)d_in[8];
    const float* ip_b2  = (const float*)d_in[9];
    const float* prep   = (const float*)d_in[10];
    const float* sig    = (const float*)d_in[11];
    const float* qff    = (const float*)d_in[12];
    const float* A_obs  = (const float*)d_in[13];
    const float* B_obs  = (const float*)d_in[14];
    const float* D_obs  = (const float*)d_in[15];
    const float* head_w = (const float*)d_in[16];
    const float* head_b = (const float*)d_in[17];
    float* out = (float*)d_out;

    k_mlp<<<64, 256>>>(t, z_t, te_w1, te_b1, te_w2, te_b2, ip_w1, ip_b1, ip_w2, ip_b2);
    k_sim<<<256, 128>>>(prep, sig, qff, A_obs, B_obs, D_obs, head_w, head_b, out);
}

// round 5
// speedup vs baseline: 1.0857x; 1.0857x over previous
#include <cuda_runtime.h>
#include <math.h>

#define FULLMASK 0xffffffffu
#define TWO_PI_F 6.2831853071795864f

// ---------------- scratch ----------------
__device__ float g_ts[256 * 256];   // ts angles, row b: [s*64 + g]

// ---------------- sim14 single-layer op schedule (32 ops) ----------------
__constant__ int c_OPC[32] = {
    -1,-1,-1,-1,-1,-1,-1,-1,
     7, 6, 5, 4, 3, 2, 1, 0,
    -1,-1,-1,-1,-1,-1,-1,-1,
     7, 0, 1, 2, 3, 4, 5, 6};
__constant__ int c_OPT[32] = {
     0, 1, 2, 3, 4, 5, 6, 7,
     0, 7, 6, 5, 4, 3, 2, 1,
     0, 1, 2, 3, 4, 5, 6, 7,
     6, 7, 0, 1, 2, 3, 4, 5};

// ---------------- helpers ----------------
__device__ __forceinline__ float g4(float4 v, int i) {
    return (i == 0) ? v.x : (i == 1) ? v.y : (i == 2) ? v.z : v.w;
}
__device__ __forceinline__ float4 splat4(float v) { return make_float4(v, v, v, v); }

// State layout (2 warps per batch element, 64 threads):
//   flat index n (10 bits): bit9..bit5 = wires 0..4 (lane bits 4..0),
//   bit4 = wire5 (WARP bit, tid bit 5), bit3 = wire6 (reg M=8),
//   bit2 = wire7 (reg M=4), bit1 = wire8/anc0, bit0 = wire9/anc1.
//   Each thread holds 16 float2 (r = bits 3..0). select index s = r & 3.
#define OIDX(n) ((n) ^ (((n) >> 5) & 31))

// RY on a lane-bit wire (no control)
__device__ __forceinline__ void ry_lane(float2 (&st)[16], int lmask, int lb, int lane,
                                        float4 c, float4 s) {
    float sg = ((lane >> lb) & 1) ? 1.f : -1.f;
    float4 sv = make_float4(g4(s,0)*sg, g4(s,1)*sg, g4(s,2)*sg, g4(s,3)*sg);
#pragma unroll
    for (int r = 0; r < 16; ++r) {
        float ox = __shfl_xor_sync(FULLMASK, st[r].x, lmask);
        float oy = __shfl_xor_sync(FULLMASK, st[r].y, lmask);
        float pc = g4(c, r & 3), ps = g4(sv, r & 3);
        st[r].x = fmaf(pc, st[r].x, ps * ox);
        st[r].y = fmaf(pc, st[r].y, ps * oy);
    }
}

// RY on a reg-bit wire (mask M)
template <int M>
__device__ __forceinline__ void ry_reg(float2 (&st)[16], float4 c, float4 s) {
#pragma unroll
    for (int r = 0; r < 16; ++r) {
        if ((r & M) == 0) {
            const int r1 = r | M;
            float pc = g4(c, r & 3), ps = g4(s, r & 3);
            float ax = st[r].x, ay = st[r].y, bx = st[r1].x, by = st[r1].y;
            st[r].x = fmaf(pc, ax, -ps * bx);
            st[r].y = fmaf(pc, ay, -ps * by);
            st[r1].x = fmaf(ps, ax, pc * bx);
            st[r1].y = fmaf(ps, ay, pc * by);
        }
    }
}

// CRX target=lane wire, control folded into (cf,sf) (identity => cf=1, sf=0)
__device__ __forceinline__ void crx_lane_f(float2 (&st)[16], int tmask,
                                           float4 cf, float4 sf) {
#pragma unroll
    for (int r = 0; r < 16; ++r) {
        float ox = __shfl_xor_sync(FULLMASK, st[r].x, tmask);
        float oy = __shfl_xor_sync(FULLMASK, st[r].y, tmask);
        float pc = g4(cf, r & 3), ps = g4(sf, r & 3);
        st[r].x = fmaf(pc, st[r].x, ps * oy);
        st[r].y = fmaf(pc, st[r].y, -ps * ox);
    }
}

// CRX target=lane wire, control = reg bit CRM (compile-time): skip inactive r
template <int CRM>
__device__ __forceinline__ void crx_lane_rc(float2 (&st)[16], int tmask,
                                            float4 c, float4 s) {
#pragma unroll
    for (int r = 0; r < 16; ++r) {
        if ((r & CRM) != 0) {
            float ox = __shfl_xor_sync(FULLMASK, st[r].x, tmask);
            float oy = __shfl_xor_sync(FULLMASK, st[r].y, tmask);
            float pc = g4(c, r & 3), ps = g4(s, r & 3);
            st[r].x = fmaf(pc, st[r].x, ps * oy);
            st[r].y = fmaf(pc, st[r].y, -ps * ox);
        }
    }
}

// CRX target=reg wire M, control folded into (cf,sf)
template <int M>
__device__ __forceinline__ void crx_reg_f(float2 (&st)[16], float4 cf, float4 sf) {
#pragma unroll
    for (int r = 0; r < 16; ++r) {
        if ((r & M) == 0) {
            const int r1 = r | M;
            float pc = g4(cf, r & 3), ps = g4(sf, r & 3);
            float ax = st[r].x, ay = st[r].y, bx = st[r1].x, by = st[r1].y;
            st[r].x  = fmaf(pc, ax, ps * by);
            st[r].y  = fmaf(pc, ay, -ps * bx);
            st[r1].x = fmaf(pc, bx, ps * ay);
            st[r1].y = fmaf(pc, by, -ps * ax);
        }
    }
}

// CRX target=reg wire M, control = reg bit CRM (compile-time): skip inactive pairs
template <int M, int CRM>
__device__ __forceinline__ void crx_reg_rc(float2 (&st)[16], float4 c, float4 s) {
#pragma unroll
    for (int r = 0; r < 16; ++r) {
        if ((r & M) == 0 && (r & CRM) != 0) {
            const int r1 = r | M;
            float pc = g4(c, r & 3), ps = g4(s, r & 3);
            float ax = st[r].x, ay = st[r].y, bx = st[r1].x, by = st[r1].y;
            st[r].x  = fmaf(pc, ax, ps * by);
            st[r].y  = fmaf(pc, ay, -ps * bx);
            st[r1].x = fmaf(pc, bx, ps * ay);
            st[r1].y = fmaf(pc, by, -ps * ax);
        }
    }
}

// RY targeting wire5 (warp bit): smem exchange
__device__ __forceinline__ void wire5_ry(float2 (&st)[16], float* sx, float* sy,
                                         int tid, int W, float4 c, float4 s) {
    __syncthreads();
#pragma unroll
    for (int r = 0; r < 16; ++r) { sx[r * 64 + tid] = st[r].x; sy[r * 64 + tid] = st[r].y; }
    __syncthreads();
    const int p = tid ^ 32;
    const float sg = W ? 1.f : -1.f;
#pragma unroll
    for (int r = 0; r < 16; ++r) {
        float ox = sx[r * 64 + p], oy = sy[r * 64 + p];
        float pc = g4(c, r & 3), ps = g4(s, r & 3) * sg;
        st[r].x = fmaf(pc, st[r].x, ps * ox);
        st[r].y = fmaf(pc, st[r].y, ps * oy);
    }
}

// CRX targeting wire5, control folded into (cf,sf)
__device__ __forceinline__ void wire5_crx(float2 (&st)[16], float* sx, float* sy,
                                          int tid, float4 cf, float4 sf) {
    __syncthreads();
#pragma unroll
    for (int r = 0; r < 16; ++r) { sx[r * 64 + tid] = st[r].x; sy[r * 64 + tid] = st[r].y; }
    __syncthreads();
    const int p = tid ^ 32;
#pragma unroll
    for (int r = 0; r < 16; ++r) {
        float ox = sx[r * 64 + p], oy = sy[r * 64 + p];
        float pc = g4(cf, r & 3), ps = g4(sf, r & 3);
        st[r].x = fmaf(pc, st[r].x, ps * oy);
        st[r].y = fmaf(pc, st[r].y, -ps * ox);
    }
}

// CRX targeting wire5, control = reg bit CRM (compile-time): exchange active r only
template <int CRM>
__device__ __forceinline__ void wire5_crx_rc(float2 (&st)[16], float* sx, float* sy,
                                             int tid, float4 c, float4 s) {
    __syncthreads();
#pragma unroll
    for (int r = 0; r < 16; ++r) {
        if ((r & CRM) != 0) { sx[r * 64 + tid] = st[r].x; sy[r * 64 + tid] = st[r].y; }
    }
    __syncthreads();
    const int p = tid ^ 32;
#pragma unroll
    for (int r = 0; r < 16; ++r) {
        if ((r & CRM) != 0) {
            float ox = sx[r * 64 + p], oy = sy[r * 64 + p];
            float pc = g4(c, r & 3), ps = g4(s, r & 3);
            st[r].x = fmaf(pc, st[r].x, ps * oy);
            st[r].y = fmaf(pc, st[r].y, -ps * ox);
        }
    }
}

// RZ on a reg-bit wire (ancilla)
template <int M>
__device__ __forceinline__ void rz_reg(float2 (&st)[16], float c, float s) {
#pragma unroll
    for (int r = 0; r < 16; ++r) {
        float ss = (r & M) ? s : -s;
        float x = st[r].x, y = st[r].y;
        st[r].x = fmaf(c, x, -ss * y);
        st[r].y = fmaf(c, y, ss * x);
    }
}

__device__ __forceinline__ void cnot_st(float2 (&st)[16]) {
#pragma unroll
    for (int r = 0; r < 16; ++r) {
        if ((r & 3) == 2) { float2 tmp = st[r]; st[r] = st[r | 1]; st[r | 1] = tmp; }
    }
}

__device__ __forceinline__ void pcphase_g(float2 (&st)[16], float cphi, float sphi) {
#pragma unroll
    for (int r = 0; r < 16; ++r) {
        float ss = ((r & 3) == 0) ? sphi : -sphi;
        float x = st[r].x, y = st[r].y;
        st[r].x = fmaf(cphi, x, -ss * y);
        st[r].y = fmaf(cphi, y, ss * x);
    }
}

// fold control activity into coefficients once per gate
__device__ __forceinline__ void fold_cs(bool act, float4 c, float4 s,
                                        float4& cf, float4& sf) {
    cf = act ? c : make_float4(1.f, 1.f, 1.f, 1.f);
    sf = act ? s : make_float4(0.f, 0.f, 0.f, 0.f);
}

__device__ __forceinline__ void apply_op(float2 (&st)[16], int lane, int W, int tid,
                                         float* sx, float* sy, int cw, int tw,
                                         float4 c, float4 s) {
    if (cw < 0) {  // RY
        if (tw < 5)       ry_lane(st, 1 << (4 - tw), 4 - tw, lane, c, s);
        else if (tw == 5) wire5_ry(st, sx, sy, tid, W, c, s);
        else if (tw == 6) ry_reg<8>(st, c, s);
        else              ry_reg<4>(st, c, s);
    } else if (cw < 5) {   // lane control: fold once (uniform over r)
        float4 cf, sf;
        fold_cs(((lane >> (4 - cw)) & 1) != 0, c, s, cf, sf);
        if (tw < 5)       crx_lane_f(st, 1 << (4 - tw), cf, sf);
        else if (tw == 5) wire5_crx(st, sx, sy, tid, cf, sf);
        else if (tw == 6) crx_reg_f<8>(st, cf, sf);
        else              crx_reg_f<4>(st, cf, sf);
    } else if (cw == 5) {  // warp control: fold once
        float4 cf, sf;
        fold_cs(W == 1, c, s, cf, sf);
        if (tw < 5)       crx_lane_f(st, 1 << (4 - tw), cf, sf);
        else              crx_reg_f<8>(st, cf, sf);       // (5,6)
    } else if (cw == 6) {  // control = reg bit 8 (compile-time skip)
        if (tw == 5)      wire5_crx_rc<8>(st, sx, sy, tid, c, s);   // (6,5)
        else              crx_reg_rc<4, 8>(st, c, s);               // (6,7)
    } else {               // cw == 7, control = reg bit 4
        if (tw == 0)      crx_lane_rc<4>(st, 16, c, s);             // (7,0)
        else              crx_reg_rc<8, 4>(st, c, s);               // (7,6)
    }
}

// 2-layer sim14 (compact loop, runtime op dispatch)
template <bool ADJ>
__device__ __forceinline__ void run_sim2l(float2 (&st)[16], int lane, int W, int tid,
                                          float* sx, float* sy,
                                          const float4* tabc, const float4* tabs) {
#pragma unroll 1
    for (int u = 0; u < 64; ++u) {
        const int step = ADJ ? (63 - u) : u;
        const int o = step & 31;
        float4 c = tabc[step];
        float4 s0 = tabs[step];
        float4 s = ADJ ? make_float4(-s0.x, -s0.y, -s0.z, -s0.w) : s0;
        apply_op(st, lane, W, tid, sx, sy, c_OPC[o], c_OPT[o], c, s);
    }
}

__device__ __forceinline__ void do_prepare(float2 (&st)[16], const float2* tabp, bool adj) {
    if (!adj) {
#pragma unroll
        for (int ly = 0; ly < 2; ++ly) {
            float2 a  = tabp[ly*4+0]; ry_reg<2>(st, splat4(a.x),  splat4(a.y));
            float2 z  = tabp[ly*4+1]; rz_reg<2>(st, z.x, z.y);
            float2 a2 = tabp[ly*4+2]; ry_reg<1>(st, splat4(a2.x), splat4(a2.y));
            float2 z2 = tabp[ly*4+3]; rz_reg<1>(st, z2.x, z2.y);
            cnot_st(st);
        }
    } else {
#pragma unroll
        for (int ly = 1; ly >= 0; --ly) {
            cnot_st(st);
            float2 z2 = tabp[ly*4+3]; rz_reg<1>(st, z2.x, -z2.y);
            float2 a2 = tabp[ly*4+2]; ry_reg<1>(st, splat4(a2.x), splat4(-a2.y));
            float2 z  = tabp[ly*4+1]; rz_reg<2>(st, z.x, -z.y);
            float2 a  = tabp[ly*4+0]; ry_reg<2>(st, splat4(a.x),  splat4(-a.y));
        }
    }
}

// ---------------- simulate kernel: 2 warps per batch element ----------------
__global__ void __launch_bounds__(64) k_sim(
    const float* __restrict__ prep_p, const float* __restrict__ sig,
    const float* __restrict__ qff,
    const float* __restrict__ A_obs, const float* __restrict__ B_obs,
    const float* __restrict__ D_obs,
    const float* __restrict__ head_w, const float* __restrict__ head_b,
    float* __restrict__ out) {
    __shared__ float sx[1024];
    __shared__ float sy[1024];
    __shared__ float4 tabc[64];
    __shared__ float4 tabs[64];
    __shared__ float2 tabq[32];
    __shared__ float2 tabp[8];
    __shared__ float2 tabsig[4];
    __shared__ float part[14];

    const int tid  = threadIdx.x;
    const int lane = tid & 31;
    const int W    = tid >> 5;
    const int b    = blockIdx.x;
    const float* tsr = g_ts + b * 256;

    if (tid < 64) {
        float c0,s0,c1,s1,c2,s2,c3,s3;
        sincosf(tsr[tid]       * 0.5f, &s0, &c0);
        sincosf(tsr[64 + tid]  * 0.5f, &s1, &c1);
        sincosf(tsr[128 + tid] * 0.5f, &s2, &c2);
        sincosf(tsr[192 + tid] * 0.5f, &s3, &c3);
        tabc[tid] = make_float4(c0, c1, c2, c3);
        tabs[tid] = make_float4(s0, s1, s2, s3);
    }
    if (tid < 32) { float sn, cc; sincosf(qff[tid] * 0.5f, &sn, &cc); tabq[tid] = make_float2(cc, sn); }
    if (tid < 8)  { float sn, cc; sincosf(prep_p[tid] * 0.5f, &sn, &cc); tabp[tid] = make_float2(cc, sn); }
    if (tid < 4)  { float sn, cc; sincosf(sig[tid], &sn, &cc); tabsig[tid] = make_float2(cc, sn); }
    __syncthreads();

    float2 st[16];
#pragma unroll
    for (int r = 0; r < 16; ++r) st[r] = make_float2(0.f, 0.f);
    if (tid == 0) st[0].x = 1.f;

    { float2 p = tabsig[0]; pcphase_g(st, p.x, p.y); }
#pragma unroll 1
    for (int k = 0; k < 3; ++k) {
        do_prepare(st, tabp, false);
        if ((k & 1) == 0) run_sim2l<false>(st, lane, W, tid, sx, sy, tabc, tabs);
        else              run_sim2l<true>(st, lane, W, tid, sx, sy, tabc, tabs);
        do_prepare(st, tabp, true);
        float2 p = tabsig[k + 1];
        pcphase_g(st, p.x, p.y);
    }
    // final sim14 with qff params, 1 layer (uniform theta)
#pragma unroll 1
    for (int step = 0; step < 32; ++step) {
        float2 tq = tabq[step];
        apply_op(st, lane, W, tid, sx, sy, c_OPC[step], c_OPT[step],
                 splat4(tq.x), splat4(tq.y));
    }

    // dump state to shared (swizzled) for expectation values
    __syncthreads();
#pragma unroll
    for (int r = 0; r < 16; ++r) {
        int n = (lane << 5) | (W << 4) | r;
        sx[OIDX(n)] = st[r].x; sy[OIDX(n)] = st[r].y;
    }
    __syncthreads();

#pragma unroll 1
    for (int w = 0; w < 7; ++w) {
        const float* Aw = A_obs + w * 6;
        const float* Bw = B_obs + w * 6;
        const float* Dw = D_obs + w * 4;
        float d0 = 2.f * Dw[1], d1 = 2.f * Dw[2], d2 = 2.f * Dw[3];
        float a10 = Aw[0], b10 = Bw[0], a20 = Aw[1], b20 = Bw[1], a21 = Aw[2], b21 = Bw[2];
        float a30 = Aw[3], b30 = Bw[3], a31 = Aw[4], b31 = Bw[4], a32 = Aw[5], b32 = Bw[5];
        int b1 = 8 - w;
        int m1 = 1 << b1, m0 = m1 << 1;
        int lowmask = m1 - 1;
        float acc = 0.f;
        for (int gi = tid; gi < 256; gi += 64) {
            int n = ((gi & ~lowmask) << 2) | (gi & lowmask);
            int i0 = OIDX(n), i1 = OIDX(n + m1), i2 = OIDX(n + m0), i3 = OIDX(n + m0 + m1);
            float2 v0 = make_float2(sx[i0], sy[i0]);
            float2 v1 = make_float2(sx[i1], sy[i1]);
            float2 v2 = make_float2(sx[i2], sy[i2]);
            float2 v3 = make_float2(sx[i3], sy[i3]);
            acc += d0 * (v0.x * v0.x + v0.y * v0.y);
            acc += d1 * (v1.x * v1.x + v1.y * v1.y);
            acc += d2 * (v2.x * v2.x + v2.y * v2.y);
#define CROSS(vi, vj, aa, bb) { \
            float pr = vi.x * vj.x + vi.y * vj.y; \
            float pim = vi.x * vj.y - vi.y * vj.x; \
            acc += 2.f * (pr * (aa) - pim * (bb)); }
            CROSS(v1, v0, a10, b10)
            CROSS(v2, v0, a20, b20)
            CROSS(v2, v1, a21, b21)
            CROSS(v3, v0, a30, b30)
            CROSS(v3, v1, a31, b31)
            CROSS(v3, v2, a32, b32)
#undef CROSS
        }
#pragma unroll
        for (int off = 16; off; off >>= 1) acc += __shfl_xor_sync(FULLMASK, acc, off);
        if (lane == 0) part[w * 2 + W] = acc;
    }
    __syncthreads();

    // head
#pragma unroll
    for (int u = 0; u < 2; ++u) {
        int j = u * 64 + tid;
        float o = head_b[j];
#pragma unroll
        for (int w = 0; w < 7; ++w) o = fmaf(part[w*2] + part[w*2+1], head_w[j * 7 + w], o);
        out[b * 128 + j] = o;
    }
}

// ---------------- fused MLP kernel: 8 batch rows per block ----------------
__device__ __forceinline__ float silu_f(float x) { return x * (1.f / (1.f + expf(-x))); }

__global__ void __launch_bounds__(256) k_mlp(
    const float* __restrict__ t, const float* __restrict__ z_t,
    const float* __restrict__ te_w1, const float* __restrict__ te_b1,
    const float* __restrict__ te_w2, const float* __restrict__ te_b2,
    const float* __restrict__ ip_w1, const float* __restrict__ ip_b1,
    const float* __restrict__ ip_w2, const float* __restrict__ ip_b2) {
    __shared__ float emb[8][128];
    __shared__ float hb[8][128];
    __shared__ float cat[8][256];
    __shared__ float g1[8][256];
    const int tid = threadIdx.x;
    const int r0 = blockIdx.x * 8;

    // stage A: sinusoidal embedding + copy z_t into cat
#pragma unroll
    for (int idx = tid; idx < 1024; idx += 256) {
        int row = idx >> 7, i = idx & 127;
        float tv = t[r0 + row];
        int ii = i & 63;
        float f = expf(-0.14391156831212787f * (float)ii);
        float a = tv * f;
        emb[row][i] = (i < 64) ? cosf(a) : sinf(a);
        cat[row][i] = z_t[(r0 + row) * 128 + i];
    }
    __syncthreads();

    // stage B: h = silu(te_w1 @ emb + te_b1); 2 half-groups of 128 threads x 4 rows
    {
        int j = tid & 127, rh = (tid >> 7) * 4;
        float acc[4];
        float bj = te_b1[j];
#pragma unroll
        for (int r = 0; r < 4; ++r) acc[r] = bj;
        const float4* w4 = reinterpret_cast<const float4*>(te_w1 + j * 128);
#pragma unroll 8
        for (int k4 = 0; k4 < 32; ++k4) {
            float4 wv = w4[k4];
#pragma unroll
            for (int r = 0; r < 4; ++r) {
                float4 x = *reinterpret_cast<const float4*>(&emb[rh + r][k4 * 4]);
                acc[r] = fmaf(wv.x, x.x, acc[r]); acc[r] = fmaf(wv.y, x.y, acc[r]);
                acc[r] = fmaf(wv.z, x.z, acc[r]); acc[r] = fmaf(wv.w, x.w, acc[r]);
            }
        }
#pragma unroll
        for (int r = 0; r < 4; ++r) hb[rh + r][j] = silu_f(acc[r]);
    }
    __syncthreads();

    // stage C: t_emb2 = te_w2 @ h + te_b2 -> cat[., 128+j]
    {
        int j = tid & 127, rh = (tid >> 7) * 4;
        float acc[4];
        float bj = te_b2[j];
#pragma unroll
        for (int r = 0; r < 4; ++r) acc[r] = bj;
        const float4* w4 = reinterpret_cast<const float4*>(te_w2 + j * 128);
#pragma unroll 8
        for (int k4 = 0; k4 < 32; ++k4) {
            float4 wv = w4[k4];
#pragma unroll
            for (int r = 0; r < 4; ++r) {
                float4 x = *reinterpret_cast<const float4*>(&hb[rh + r][k4 * 4]);
                acc[r] = fmaf(wv.x, x.x, acc[r]); acc[r] = fmaf(wv.y, x.y, acc[r]);
                acc[r] = fmaf(wv.z, x.z, acc[r]); acc[r] = fmaf(wv.w, x.w, acc[r]);
            }
        }
#pragma unroll
        for (int r = 0; r < 4; ++r) cat[rh + r][128 + j] = acc[r];
    }
    __syncthreads();

    // stage D: g1 = silu(ip_w1 @ cat + ip_b1); 256 threads x 8 rows
    {
        int j = tid;
        float acc[8];
        float bj = ip_b1[j];
#pragma unroll
        for (int r = 0; r < 8; ++r) acc[r] = bj;
        const float4* w4 = reinterpret_cast<const float4*>(ip_w1 + j * 256);
#pragma unroll 4
        for (int k4 = 0; k4 < 64; ++k4) {
            float4 wv = w4[k4];
#pragma unroll
            for (int r = 0; r < 8; ++r) {
                float4 x = *reinterpret_cast<const float4*>(&cat[r][k4 * 4]);
                acc[r] = fmaf(wv.x, x.x, acc[r]); acc[r] = fmaf(wv.y, x.y, acc[r]);
                acc[r] = fmaf(wv.z, x.z, acc[r]); acc[r] = fmaf(wv.w, x.w, acc[r]);
            }
        }
#pragma unroll
        for (int r = 0; r < 8; ++r) g1[r][j] = silu_f(acc[r]);
    }
    __syncthreads();

    // stage E: ts = sigmoid(ip_w2 @ g1 + ip_b2) * 2pi
    {
        int j = tid;
        float acc[8];
        float bj = ip_b2[j];
#pragma unroll
        for (int r = 0; r < 8; ++r) acc[r] = bj;
        const float4* w4 = reinterpret_cast<const float4*>(ip_w2 + j * 256);
#pragma unroll 4
        for (int k4 = 0; k4 < 64; ++k4) {
            float4 wv = w4[k4];
#pragma unroll
            for (int r = 0; r < 8; ++r) {
                float4 x = *reinterpret_cast<const float4*>(&g1[r][k4 * 4]);
                acc[r] = fmaf(wv.x, x.x, acc[r]); acc[r] = fmaf(wv.y, x.y, acc[r]);
                acc[r] = fmaf(wv.z, x.z, acc[r]); acc[r] = fmaf(wv.w, x.w, acc[r]);
            }
        }
#pragma unroll
        for (int r = 0; r < 8; ++r)
            g_ts[(r0 + r) * 256 + j] = TWO_PI_F / (1.f + expf(-acc[r]));
    }
}

// ---------------- launch ----------------
extern "C" void kernel_launch(void* const* d_in, const int* in_sizes, int n_in,
                              void* d_out, int out_size) {
    const float* z_t    = (const float*)d_in[0];
    const float* t      = (const float*)d_in[1];
    const float* te_w1  = (const float*)d_in[2];
    const float* te_b1  = (const float*)d_in[3];
    const float* te_w2  = (const float*)d_in[4];
    const float* te_b2  = (const float*)d_in[5];
    const float* ip_w1  = (const float*)d_in[6];
    const float* ip_b1  = (const float*)d_in[7];
    const float* ip_w2  = (const float*)d_in[8];
    const float* ip_b2  = (const float*)d_in[9];
    const float* prep   = (const float*)d_in[10];
    const float* sig    = (const float*)d_in[11];
    const float* qff    = (const float*)d_in[12];
    const float* A_obs  = (const float*)d_in[13];
    const float* B_obs  = (const float*)d_in[14];
    const float* D_obs  = (const float*)d_in[15];
    const float* head_w = (const float*)d_in[16];
    const float* head_b = (const float*)d_in[17];
    float* out = (float*)d_out;

    k_mlp<<<32, 256>>>(t, z_t, te_w1, te_b1, te_w2, te_b2, ip_w1, ip_b1, ip_w2, ip_b2);
    k_sim<<<256, 64>>>(prep, sig, qff, A_obs, B_obs, D_obs, head_w, head_b, out);
}

// round 9
// speedup vs baseline: 1.7489x; 1.6107x over previous
#include <cuda_runtime.h>
#include <math.h>

#define FULLMASK 0xffffffffu
#define TWO_PI_F 6.2831853071795864f

typedef unsigned long long u64;

// ---------------- f32x2 packed helpers (sm_103a) ----------------
__device__ __forceinline__ u64 pk2(float lo, float hi) {
    u64 r; asm("mov.b64 %0,{%1,%2};" : "=l"(r) : "f"(lo), "f"(hi)); return r;
}
__device__ __forceinline__ u64 f2fma(u64 a, u64 b, u64 c) {
    u64 d; asm("fma.rn.f32x2 %0,%1,%2,%3;" : "=l"(d) : "l"(a), "l"(b), "l"(c)); return d;
}
__device__ __forceinline__ u64 f2mul(u64 a, u64 b) {
    u64 d; asm("mul.rn.f32x2 %0,%1,%2;" : "=l"(d) : "l"(a), "l"(b)); return d;
}
#define U64REF(f2v) (*reinterpret_cast<u64*>(&(f2v)))

// ---------------- scratch ----------------
__device__ float g_ts[256 * 256];   // ts angles, row b: [s*64 + g]

// ---------------- sim14 single-layer op schedule (32 ops) ----------------
__constant__ int c_OPC[32] = {
    -1,-1,-1,-1,-1,-1,-1,-1,
     7, 6, 5, 4, 3, 2, 1, 0,
    -1,-1,-1,-1,-1,-1,-1,-1,
     7, 0, 1, 2, 3, 4, 5, 6};
__constant__ int c_OPT[32] = {
     0, 1, 2, 3, 4, 5, 6, 7,
     0, 7, 6, 5, 4, 3, 2, 1,
     0, 1, 2, 3, 4, 5, 6, 7,
     6, 7, 0, 1, 2, 3, 4, 5};

// ---------------- helpers ----------------
__device__ __forceinline__ float g4(float4 v, int i) {
    return (i == 0) ? v.x : (i == 1) ? v.y : (i == 2) ? v.z : v.w;
}
__device__ __forceinline__ float4 splat4(float v) { return make_float4(v, v, v, v); }

// State layout (2 warps per batch element, 64 threads):
//   flat index n (10 bits): bit9..bit5 = wires 0..4 (lane bits 4..0),
//   bit4 = wire5 (WARP bit, tid bit 5), bit3 = wire6 (reg M=8),
//   bit2 = wire7 (reg M=4), bit1 = wire8/anc0, bit0 = wire9/anc1.
//   Each thread holds 16 float2 (r = bits 3..0). select index s = r & 3.
#define OIDX(n) ((n) ^ (((n) >> 5) & 31))

// RY on a lane-bit wire: v' = c*v + s_signed*o   (f32x2, 64-bit shuffle)
__device__ __forceinline__ void ry_lane(float2 (&st)[16], int lmask, int lb, int lane,
                                        float4 c, float4 s) {
    float sg = ((lane >> lb) & 1) ? 1.f : -1.f;
    u64 c2[4], s2[4];
#pragma unroll
    for (int i = 0; i < 4; ++i) {
        float pc = g4(c, i), ps = g4(s, i) * sg;
        c2[i] = pk2(pc, pc); s2[i] = pk2(ps, ps);
    }
#pragma unroll
    for (int r = 0; r < 16; ++r) {
        u64 v = U64REF(st[r]);
        u64 o = __shfl_xor_sync(FULLMASK, v, lmask);
        U64REF(st[r]) = f2fma(c2[r & 3], v, f2mul(s2[r & 3], o));
    }
}

// RY on a reg-bit wire (mask M): a' = c*a - s*b ; b' = s*a + c*b   (f32x2)
template <int M>
__device__ __forceinline__ void ry_reg(float2 (&st)[16], float4 c, float4 s) {
    u64 c2[4], s2[4], ns2[4];
#pragma unroll
    for (int i = 0; i < 4; ++i) {
        float pc = g4(c, i), ps = g4(s, i);
        c2[i] = pk2(pc, pc); s2[i] = pk2(ps, ps); ns2[i] = pk2(-ps, -ps);
    }
#pragma unroll
    for (int r = 0; r < 16; ++r) {
        if ((r & M) == 0) {
            const int r1 = r | M, i = r & 3;
            u64 a = U64REF(st[r]);
            u64 b = U64REF(st[r1]);
            U64REF(st[r])  = f2fma(ns2[i], b, f2mul(c2[i], a));
            U64REF(st[r1]) = f2fma(s2[i],  a, f2mul(c2[i], b));
        }
    }
}

// CRX target=lane wire: nx = c*x + s*oy ; ny = c*y - s*ox  (predicated store kept)
__device__ __forceinline__ void crx_lane(float2 (&st)[16], int tmask,
                                         bool actBase, int crm,
                                         float4 c, float4 s) {
    u64 c2[4], sm2[4];   // sm2 = (ps, -ps)
#pragma unroll
    for (int i = 0; i < 4; ++i) {
        float pc = g4(c, i), ps = g4(s, i);
        c2[i] = pk2(pc, pc); sm2[i] = pk2(ps, -ps);
    }
#pragma unroll
    for (int r = 0; r < 16; ++r) {
        float ox = __shfl_xor_sync(FULLMASK, st[r].x, tmask);
        float oy = __shfl_xor_sync(FULLMASK, st[r].y, tmask);
        bool act = actBase && (crm == 0 || (r & crm) != 0);
        u64 osw = pk2(oy, ox);
        u64 v = U64REF(st[r]);
        u64 nv = f2fma(c2[r & 3], v, f2mul(sm2[r & 3], osw));
        if (act) U64REF(st[r]) = nv;
    }
}

// CRX target=reg wire M: n0 = c*a + sm*(by,bx) ; n1 = c*b + sm*(ay,ax)
template <int M>
__device__ __forceinline__ void crx_reg(float2 (&st)[16], bool actBase, int crm,
                                        float4 c, float4 s) {
    u64 c2[4], sm2[4];
#pragma unroll
    for (int i = 0; i < 4; ++i) {
        float pc = g4(c, i), ps = g4(s, i);
        c2[i] = pk2(pc, pc); sm2[i] = pk2(ps, -ps);
    }
#pragma unroll
    for (int r = 0; r < 16; ++r) {
        if ((r & M) == 0) {
            const int r1 = r | M, i = r & 3;
            bool act = actBase && (crm == 0 || (r & crm) != 0);
            float2 fa = st[r], fb = st[r1];
            u64 a = U64REF(st[r]);
            u64 b = U64REF(st[r1]);
            u64 bsw = pk2(fb.y, fb.x);
            u64 asw = pk2(fa.y, fa.x);
            u64 n0 = f2fma(c2[i], a, f2mul(sm2[i], bsw));
            u64 n1 = f2fma(c2[i], b, f2mul(sm2[i], asw));
            if (act) { U64REF(st[r]) = n0; U64REF(st[r1]) = n1; }
        }
    }
}

// Op (RY or CRX) whose target is wire 5 (the warp bit): smem exchange (round-2 form)
__device__ __forceinline__ void wire5_op(float2 (&st)[16], float* sx, float* sy,
                                         int tid, int W, bool isRY,
                                         bool actBase, int crm,
                                         float4 c, float4 s) {
    __syncthreads();
#pragma unroll
    for (int r = 0; r < 16; ++r) { sx[r * 64 + tid] = st[r].x; sy[r * 64 + tid] = st[r].y; }
    __syncthreads();
    const int p = tid ^ 32;
#pragma unroll
    for (int r = 0; r < 16; ++r) {
        float ox = sx[r * 64 + p], oy = sy[r * 64 + p];
        float pc = g4(c, r & 3), ps = g4(s, r & 3);
        if (isRY) {
            float sg = W ? ps : -ps;
            st[r].x = fmaf(pc, st[r].x, sg * ox);
            st[r].y = fmaf(pc, st[r].y, sg * oy);
        } else {
            bool act = actBase && (crm == 0 || (r & crm) != 0);
            float nx = fmaf(pc, st[r].x, ps * oy);
            float ny = fmaf(pc, st[r].y, -ps * ox);
            if (act) { st[r].x = nx; st[r].y = ny; }
        }
    }
}

// RZ on a reg-bit wire (ancilla): x'=c*x-ss*y ; y'=c*y+ss*x  (f32x2 via swap)
template <int M>
__device__ __forceinline__ void rz_reg(float2 (&st)[16], float c, float s) {
    u64 c2 = pk2(c, c);
    u64 sp = pk2(-s, s);   // r&M set:   ss = +s -> (-s, s)
    u64 sm = pk2(s, -s);   // r&M clear: ss = -s -> ( s,-s)
#pragma unroll
    for (int r = 0; r < 16; ++r) {
        float2 f = st[r];
        u64 sw = pk2(f.y, f.x);
        u64 v = U64REF(st[r]);
        U64REF(st[r]) = f2fma(c2, v, f2mul((r & M) ? sp : sm, sw));
    }
}

__device__ __forceinline__ void cnot_st(float2 (&st)[16]) {
#pragma unroll
    for (int r = 0; r < 16; ++r) {
        if ((r & 3) == 2) { float2 tmp = st[r]; st[r] = st[r | 1]; st[r | 1] = tmp; }
    }
}

// pcphase: x'=cphi*x-ss*y ; y'=cphi*y+ss*x with ss = (r&3==0)? sphi : -sphi
__device__ __forceinline__ void pcphase_g(float2 (&st)[16], float cphi, float sphi) {
    u64 c2 = pk2(cphi, cphi);
    u64 sp = pk2(-sphi, sphi);
    u64 sm = pk2(sphi, -sphi);
#pragma unroll
    for (int r = 0; r < 16; ++r) {
        float2 f = st[r];
        u64 sw = pk2(f.y, f.x);
        u64 v = U64REF(st[r]);
        U64REF(st[r]) = f2fma(c2, v, f2mul(((r & 3) == 0) ? sp : sm, sw));
    }
}

__device__ __forceinline__ void apply_op(float2 (&st)[16], int lane, int W, int tid,
                                         float* sx, float* sy,
                                         int cw, int tw, float4 c, float4 s) {
    if (cw < 0) {  // RY
        if (tw < 5)       ry_lane(st, 1 << (4 - tw), 4 - tw, lane, c, s);
        else if (tw == 5) wire5_op(st, sx, sy, tid, W, true, true, 0, c, s);
        else if (tw == 6) ry_reg<8>(st, c, s);
        else              ry_reg<4>(st, c, s);
    } else {       // CRX
        bool actBase; int crm = 0;
        if (cw < 5)       actBase = ((lane >> (4 - cw)) & 1) != 0;
        else if (cw == 5) actBase = (W == 1);
        else { actBase = true; crm = (cw == 6) ? 8 : 4; }
        if (tw < 5)       crx_lane(st, 1 << (4 - tw), actBase, crm, c, s);
        else if (tw == 5) wire5_op(st, sx, sy, tid, W, false, actBase, crm, c, s);
        else if (tw == 6) crx_reg<8>(st, actBase, crm, c, s);
        else              crx_reg<4>(st, actBase, crm, c, s);
    }
}

// sim14 with 2 layers, theta per-ancilla from tab[step*4 + s] = (cos(th/2), sin(th/2))
__device__ __forceinline__ void run_sim14_2l(float2 (&st)[16], int lane, int W, int tid,
                                             float* sx, float* sy,
                                             const float2* tab, bool adj) {
    if (!adj) {
#pragma unroll 1
        for (int step = 0; step < 64; ++step) {
            int o = step & 31;
            float2 t0 = tab[step*4+0], t1 = tab[step*4+1], t2 = tab[step*4+2], t3 = tab[step*4+3];
            float4 c = make_float4(t0.x, t1.x, t2.x, t3.x);
            float4 s = make_float4(t0.y, t1.y, t2.y, t3.y);
            apply_op(st, lane, W, tid, sx, sy, c_OPC[o], c_OPT[o], c, s);
        }
    } else {
#pragma unroll 1
        for (int step = 63; step >= 0; --step) {
            int o = step & 31;
            float2 t0 = tab[step*4+0], t1 = tab[step*4+1], t2 = tab[step*4+2], t3 = tab[step*4+3];
            float4 c = make_float4(t0.x, t1.x, t2.x, t3.x);
            float4 s = make_float4(-t0.y, -t1.y, -t2.y, -t3.y);
            apply_op(st, lane, W, tid, sx, sy, c_OPC[o], c_OPT[o], c, s);
        }
    }
}

__device__ __forceinline__ void do_prepare(float2 (&st)[16], const float2* tabp, bool adj) {
    if (!adj) {
#pragma unroll
        for (int ly = 0; ly < 2; ++ly) {
            float2 a  = tabp[ly*4+0]; ry_reg<2>(st, splat4(a.x),  splat4(a.y));
            float2 z  = tabp[ly*4+1]; rz_reg<2>(st, z.x, z.y);
            float2 a2 = tabp[ly*4+2]; ry_reg<1>(st, splat4(a2.x), splat4(a2.y));
            float2 z2 = tabp[ly*4+3]; rz_reg<1>(st, z2.x, z2.y);
            cnot_st(st);
        }
    } else {
#pragma unroll
        for (int ly = 1; ly >= 0; --ly) {
            cnot_st(st);
            float2 z2 = tabp[ly*4+3]; rz_reg<1>(st, z2.x, -z2.y);
            float2 a2 = tabp[ly*4+2]; ry_reg<1>(st, splat4(a2.x), splat4(-a2.y));
            float2 z  = tabp[ly*4+1]; rz_reg<2>(st, z.x, -z.y);
            float2 a  = tabp[ly*4+0]; ry_reg<2>(st, splat4(a.x),  splat4(-a.y));
        }
    }
}

// ---------------- simulate kernel: 2 warps per batch element ----------------
__global__ void __launch_bounds__(64) k_sim(
    const float* __restrict__ prep_p, const float* __restrict__ sig,
    const float* __restrict__ qff,
    const float* __restrict__ A_obs, const float* __restrict__ B_obs,
    const float* __restrict__ D_obs,
    const float* __restrict__ head_w, const float* __restrict__ head_b,
    float* __restrict__ out) {
    __shared__ float sx[1024];      // exchange / obs real
    __shared__ float sy[1024];      // exchange / obs imag
    __shared__ float2 tabsel[256];  // [g*4 + s]
    __shared__ float2 tabq[32];
    __shared__ float2 tabp[8];
    __shared__ float2 tabsig[4];
    __shared__ float part[14];

    const int tid  = threadIdx.x;
    const int lane = tid & 31;
    const int W    = tid >> 5;
    const int b    = blockIdx.x;
    const float* tsr = g_ts + b * 256;

    for (int i = tid; i < 256; i += 64) {
        int s = i >> 6, g = i & 63;
        float sn, cc; sincosf(tsr[i] * 0.5f, &sn, &cc);
        tabsel[g * 4 + s] = make_float2(cc, sn);
    }
    if (tid < 32) { float sn, cc; sincosf(qff[tid] * 0.5f, &sn, &cc); tabq[tid] = make_float2(cc, sn); }
    if (tid < 8)  { float sn, cc; sincosf(prep_p[tid] * 0.5f, &sn, &cc); tabp[tid] = make_float2(cc, sn); }
    if (tid < 4)  { float sn, cc; sincosf(sig[tid], &sn, &cc); tabsig[tid] = make_float2(cc, sn); }
    __syncthreads();

    float2 st[16];
#pragma unroll
    for (int r = 0; r < 16; ++r) st[r] = make_float2(0.f, 0.f);
    if (tid == 0) st[0].x = 1.f;

    { float2 p = tabsig[0]; pcphase_g(st, p.x, p.y); }
#pragma unroll 1
    for (int k = 0; k < 3; ++k) {
        do_prepare(st, tabp, false);
        run_sim14_2l(st, lane, W, tid, sx, sy, tabsel, (k & 1) != 0);
        do_prepare(st, tabp, true);
        float2 p = tabsig[k + 1];
        pcphase_g(st, p.x, p.y);
    }
    // final sim14 with qff params, 1 layer
#pragma unroll 1
    for (int step = 0; step < 32; ++step) {
        float2 tq = tabq[step];
        apply_op(st, lane, W, tid, sx, sy, c_OPC[step], c_OPT[step],
                 splat4(tq.x), splat4(tq.y));
    }

    // dump state to shared (swizzled) for expectation values
    __syncthreads();
#pragma unroll
    for (int r = 0; r < 16; ++r) {
        int n = (lane << 5) | (W << 4) | r;
        sx[OIDX(n)] = st[r].x; sy[OIDX(n)] = st[r].y;
    }
    __syncthreads();

#pragma unroll 1
    for (int w = 0; w < 7; ++w) {
        const float* Aw = A_obs + w * 6;
        const float* Bw = B_obs + w * 6;
        const float* Dw = D_obs + w * 4;
        float d0 = 2.f * Dw[1], d1 = 2.f * Dw[2], d2 = 2.f * Dw[3];
        float a10 = Aw[0], b10 = Bw[0], a20 = Aw[1], b20 = Bw[1], a21 = Aw[2], b21 = Bw[2];
        float a30 = Aw[3], b30 = Bw[3], a31 = Aw[4], b31 = Bw[4], a32 = Aw[5], b32 = Bw[5];
        int b1 = 8 - w;
        int m1 = 1 << b1, m0 = m1 << 1;
        int lowmask = m1 - 1;
        float acc = 0.f;
        for (int gi = tid; gi < 256; gi += 64) {
            int n = ((gi & ~lowmask) << 2) | (gi & lowmask);
            int i0 = OIDX(n), i1 = OIDX(n + m1), i2 = OIDX(n + m0), i3 = OIDX(n + m0 + m1);
            float2 v0 = make_float2(sx[i0], sy[i0]);
            float2 v1 = make_float2(sx[i1], sy[i1]);
            float2 v2 = make_float2(sx[i2], sy[i2]);
            float2 v3 = make_float2(sx[i3], sy[i3]);
            acc += d0 * (v0.x * v0.x + v0.y * v0.y);
            acc += d1 * (v1.x * v1.x + v1.y * v1.y);
            acc += d2 * (v2.x * v2.x + v2.y * v2.y);
#define CROSS(vi, vj, aa, bb) { \
            float pr = vi.x * vj.x + vi.y * vj.y; \
            float pim = vi.x * vj.y - vi.y * vj.x; \
            acc += 2.f * (pr * (aa) - pim * (bb)); }
            CROSS(v1, v0, a10, b10)
            CROSS(v2, v0, a20, b20)
            CROSS(v2, v1, a21, b21)
            CROSS(v3, v0, a30, b30)
            CROSS(v3, v1, a31, b31)
            CROSS(v3, v2, a32, b32)
#undef CROSS
        }
#pragma unroll
        for (int off = 16; off; off >>= 1) acc += __shfl_xor_sync(FULLMASK, acc, off);
        if (lane == 0) part[w * 2 + W] = acc;
    }
    __syncthreads();

    // head: out[b][j] = sum_w e[w] * head_w[j*7+w] + head_b[j]
#pragma unroll
    for (int u = 0; u < 2; ++u) {
        int j = u * 64 + tid;
        float o = head_b[j];
#pragma unroll
        for (int w = 0; w < 7; ++w) o = fmaf(part[w*2] + part[w*2+1], head_w[j * 7 + w], o);
        out[b * 128 + j] = o;
    }
}

// ---------------- fused MLP kernel: 2 batch rows per block (round-2) ----------------
__device__ __forceinline__ float silu_f(float x) { return x * (1.f / (1.f + expf(-x))); }

__global__ void __launch_bounds__(256) k_mlp(
    const float* __restrict__ t, const float* __restrict__ z_t,
    const float* __restrict__ te_w1, const float* __restrict__ te_b1,
    const float* __restrict__ te_w2, const float* __restrict__ te_b2,
    const float* __restrict__ ip_w1, const float* __restrict__ ip_b1,
    const float* __restrict__ ip_w2, const float* __restrict__ ip_b2) {
    __shared__ float emb[2][128];
    __shared__ float hb[2][128];
    __shared__ float cat[2][256];
    __shared__ float g1[2][256];
    const int tid = threadIdx.x;
    const int r0 = blockIdx.x * 2;

    // stage A: sinusoidal embedding + copy z_t into cat
    {
        int row = tid >> 7, i = tid & 127;
        float tv = t[r0 + row];
        int ii = i & 63;
        float f = expf(-0.14391156831212787f * (float)ii);
        float a = tv * f;
        emb[row][i] = (i < 64) ? cosf(a) : sinf(a);
        cat[row][i] = z_t[(r0 + row) * 128 + i];
    }
    __syncthreads();

    // stage B: h = silu(te_w1 @ emb + te_b1)
    if (tid < 128) {
        int j = tid;
        float a0 = te_b1[j], a1 = a0;
        const float4* w4 = reinterpret_cast<const float4*>(te_w1 + j * 128);
#pragma unroll 8
        for (int k4 = 0; k4 < 32; ++k4) {
            float4 wv = w4[k4];
            float4 x0 = *reinterpret_cast<const float4*>(&emb[0][k4 * 4]);
            float4 x1 = *reinterpret_cast<const float4*>(&emb[1][k4 * 4]);
            a0 = fmaf(wv.x, x0.x, a0); a0 = fmaf(wv.y, x0.y, a0);
            a0 = fmaf(wv.z, x0.z, a0); a0 = fmaf(wv.w, x0.w, a0);
            a1 = fmaf(wv.x, x1.x, a1); a1 = fmaf(wv.y, x1.y, a1);
            a1 = fmaf(wv.z, x1.z, a1); a1 = fmaf(wv.w, x1.w, a1);
        }
        hb[0][j] = silu_f(a0); hb[1][j] = silu_f(a1);
    }
    __syncthreads();

    // stage C: t_emb2 = te_w2 @ h + te_b2 -> cat[., 128+j]
    if (tid < 128) {
        int j = tid;
        float a0 = te_b2[j], a1 = a0;
        const float4* w4 = reinterpret_cast<const float4*>(te_w2 + j * 128);
#pragma unroll 8
        for (int k4 = 0; k4 < 32; ++k4) {
            float4 wv = w4[k4];
            float4 x0 = *reinterpret_cast<const float4*>(&hb[0][k4 * 4]);
            float4 x1 = *reinterpret_cast<const float4*>(&hb[1][k4 * 4]);
            a0 = fmaf(wv.x, x0.x, a0); a0 = fmaf(wv.y, x0.y, a0);
            a0 = fmaf(wv.z, x0.z, a0); a0 = fmaf(wv.w, x0.w, a0);
            a1 = fmaf(wv.x, x1.x, a1); a1 = fmaf(wv.y, x1.y, a1);
            a1 = fmaf(wv.z, x1.z, a1); a1 = fmaf(wv.w, x1.w, a1);
        }
        cat[0][128 + j] = a0; cat[1][128 + j] = a1;
    }
    __syncthreads();

    // stage D: g1 = silu(ip_w1 @ cat + ip_b1)
    {
        int j = tid;
        float a0 = ip_b1[j], a1 = a0;
        const float4* w4 = reinterpret_cast<const float4*>(ip_w1 + j * 256);
#pragma unroll 8
        for (int k4 = 0; k4 < 64; ++k4) {
            float4 wv = w4[k4];
            float4 x0 = *reinterpret_cast<const float4*>(&cat[0][k4 * 4]);
            float4 x1 = *reinterpret_cast<const float4*>(&cat[1][k4 * 4]);
            a0 = fmaf(wv.x, x0.x, a0); a0 = fmaf(wv.y, x0.y, a0);
            a0 = fmaf(wv.z, x0.z, a0); a0 = fmaf(wv.w, x0.w, a0);
            a1 = fmaf(wv.x, x1.x, a1); a1 = fmaf(wv.y, x1.y, a1);
            a1 = fmaf(wv.z, x1.z, a1); a1 = fmaf(wv.w, x1.w, a1);
        }
        g1[0][j] = silu_f(a0); g1[1][j] = silu_f(a1);
    }
    __syncthreads();

    // stage E: ts = sigmoid(ip_w2 @ g1 + ip_b2) * 2pi
    {
        int j = tid;
        float a0 = ip_b2[j], a1 = a0;
        const float4* w4 = reinterpret_cast<const float4*>(ip_w2 + j * 256);
#pragma unroll 8
        for (int k4 = 0; k4 < 64; ++k4) {
            float4 wv = w4[k4];
            float4 x0 = *reinterpret_cast<const float4*>(&g1[0][k4 * 4]);
            float4 x1 = *reinterpret_cast<const float4*>(&g1[1][k4 * 4]);
            a0 = fmaf(wv.x, x0.x, a0); a0 = fmaf(wv.y, x0.y, a0);
            a0 = fmaf(wv.z, x0.z, a0); a0 = fmaf(wv.w, x0.w, a0);
            a1 = fmaf(wv.x, x1.x, a1); a1 = fmaf(wv.y, x1.y, a1);
            a1 = fmaf(wv.z, x1.z, a1); a1 = fmaf(wv.w, x1.w, a1);
        }
        g_ts[r0 * 256 + j]       = TWO_PI_F / (1.f + expf(-a0));
        g_ts[(r0 + 1) * 256 + j] = TWO_PI_F / (1.f + expf(-a1));
    }
}

// ---------------- launch ----------------
extern "C" void kernel_launch(void* const* d_in, const int* in_sizes, int n_in,
                              void* d_out, int out_size) {
    const float* z_t    = (const float*)d_in[0];
    const float* t      = (const float*)d_in[1];
    const float* te_w1  = (const float*)d_in[2];
    const float* te_b1  = (const float*)d_in[3];
    const float* te_w2  = (const float*)d_in[4];
    const float* te_b2  = (const float*)d_in[5];
    const float* ip_w1  = (const float*)d_in[6];
    const float* ip_b1  = (const float*)d_in[7];
    const float* ip_w2  = (const float*)d_in[8];
    const float* ip_b2  = (const float*)d_in[9];
    const float* prep   = (const float*)d_in[10];
    const float* sig    = (const float*)d_in[11];
    const float* qff    = (const float*)d_in[12];
    const float* A_obs  = (const float*)d_in[13];
    const float* B_obs  = (const float*)d_in[14];
    const float* D_obs  = (const float*)d_in[15];
    const float* head_w = (const float*)d_in[16];
    const float* head_b = (const float*)d_in[17];
    float* out = (float*)d_out;

    k_mlp<<<128, 256>>>(t, z_t, te_w1, te_b1, te_w2, te_b2, ip_w1, ip_b1, ip_w2, ip_b2);
    k_sim<<<256, 64>>>(prep, sig, qff, A_obs, B_obs, D_obs, head_w, head_b, out);
}

// round 10
// speedup vs baseline: 1.8017x; 1.0302x over previous
#include <cuda_runtime.h>
#include <math.h>

#define FULLMASK 0xffffffffu
#define TWO_PI_F 6.2831853071795864f

// ---------------- scratch ----------------
__device__ float g_ts[256 * 256];   // ts angles, row b: [s*64 + g]

// ---------------- sim14 single-layer op schedule (32 ops) ----------------
__constant__ int c_OPC[32] = {
    -1,-1,-1,-1,-1,-1,-1,-1,
     7, 6, 5, 4, 3, 2, 1, 0,
    -1,-1,-1,-1,-1,-1,-1,-1,
     7, 0, 1, 2, 3, 4, 5, 6};
__constant__ int c_OPT[32] = {
     0, 1, 2, 3, 4, 5, 6, 7,
     0, 7, 6, 5, 4, 3, 2, 1,
     0, 1, 2, 3, 4, 5, 6, 7,
     6, 7, 0, 1, 2, 3, 4, 5};

// ---------------- helpers ----------------
__device__ __forceinline__ float g4(float4 v, int i) {
    return (i == 0) ? v.x : (i == 1) ? v.y : (i == 2) ? v.z : v.w;
}
__device__ __forceinline__ float4 splat4(float v) { return make_float4(v, v, v, v); }

// State layout (2 warps per batch element, 64 threads):
//   flat index n (10 bits): bit9..bit5 = wires 0..4 (lane bits 4..0),
//   bit4 = wire5 (WARP bit, tid bit 5), bit3 = wire6 (reg M=8),
//   bit2 = wire7 (reg M=4), bit1 = wire8/anc0, bit0 = wire9/anc1.
//   Each thread holds 16 float2 (r = bits 3..0). select index s = r & 3.
#define OIDX(n) ((n) ^ (((n) >> 5) & 31))

// RY on a lane-bit wire
__device__ __forceinline__ void ry_lane(float2 (&st)[16], int lmask, int lb, int lane,
                                        float4 c, float4 s) {
    float sg = ((lane >> lb) & 1) ? 1.f : -1.f;
    float4 sv = make_float4(g4(s,0)*sg, g4(s,1)*sg, g4(s,2)*sg, g4(s,3)*sg);
#pragma unroll
    for (int r = 0; r < 16; ++r) {
        float ox = __shfl_xor_sync(FULLMASK, st[r].x, lmask);
        float oy = __shfl_xor_sync(FULLMASK, st[r].y, lmask);
        float pc = g4(c, r & 3), ps = g4(sv, r & 3);
        st[r].x = fmaf(pc, st[r].x, ps * ox);
        st[r].y = fmaf(pc, st[r].y, ps * oy);
    }
}

// RY on a reg-bit wire (mask M in {8,4,2,1})
template <int M>
__device__ __forceinline__ void ry_reg(float2 (&st)[16], float4 c, float4 s) {
#pragma unroll
    for (int r = 0; r < 16; ++r) {
        if ((r & M) == 0) {
            const int r1 = r | M;
            float pc = g4(c, r & 3), ps = g4(s, r & 3);
            float ax = st[r].x, ay = st[r].y, bx = st[r1].x, by = st[r1].y;
            st[r].x = fmaf(pc, ax, -ps * bx);
            st[r].y = fmaf(pc, ay, -ps * by);
            st[r1].x = fmaf(ps, ax, pc * bx);
            st[r1].y = fmaf(ps, ay, pc * by);
        }
    }
}

// CRX with target on a lane-bit wire. act = actBase && (crm==0 || (r&crm))
__device__ __forceinline__ void crx_lane(float2 (&st)[16], int tmask,
                                         bool actBase, int crm,
                                         float4 c, float4 s) {
#pragma unroll
    for (int r = 0; r < 16; ++r) {
        float ox = __shfl_xor_sync(FULLMASK, st[r].x, tmask);
        float oy = __shfl_xor_sync(FULLMASK, st[r].y, tmask);
        bool act = actBase && (crm == 0 || (r & crm) != 0);
        float pc = g4(c, r & 3), ps = g4(s, r & 3);
        float nx = fmaf(pc, st[r].x, ps * oy);
        float ny = fmaf(pc, st[r].y, -ps * ox);
        if (act) { st[r].x = nx; st[r].y = ny; }
    }
}

// CRX with target on a reg-bit wire (mask M)
template <int M>
__device__ __forceinline__ void crx_reg(float2 (&st)[16], bool actBase, int crm,
                                        float4 c, float4 s) {
#pragma unroll
    for (int r = 0; r < 16; ++r) {
        if ((r & M) == 0) {
            const int r1 = r | M;
            bool act = actBase && (crm == 0 || (r & crm) != 0);
            float pc = g4(c, r & 3), ps = g4(s, r & 3);
            float ax = st[r].x, ay = st[r].y, bx = st[r1].x, by = st[r1].y;
            float n0x = fmaf(pc, ax, ps * by);
            float n0y = fmaf(pc, ay, -ps * bx);
            float n1x = fmaf(pc, bx, ps * ay);
            float n1y = fmaf(pc, by, -ps * ax);
            if (act) { st[r] = make_float2(n0x, n0y); st[r1] = make_float2(n1x, n1y); }
        }
    }
}

// Op (RY or CRX) whose target is wire 5 (the warp bit): smem exchange.
__device__ __forceinline__ void wire5_op(float2 (&st)[16], float* sx, float* sy,
                                         int tid, int W, bool isRY,
                                         bool actBase, int crm,
                                         float4 c, float4 s) {
    __syncthreads();
#pragma unroll
    for (int r = 0; r < 16; ++r) { sx[r * 64 + tid] = st[r].x; sy[r * 64 + tid] = st[r].y; }
    __syncthreads();
    const int p = tid ^ 32;
#pragma unroll
    for (int r = 0; r < 16; ++r) {
        float ox = sx[r * 64 + p], oy = sy[r * 64 + p];
        float pc = g4(c, r & 3), ps = g4(s, r & 3);
        if (isRY) {
            float sg = W ? ps : -ps;
            st[r].x = fmaf(pc, st[r].x, sg * ox);
            st[r].y = fmaf(pc, st[r].y, sg * oy);
        } else {
            bool act = actBase && (crm == 0 || (r & crm) != 0);
            float nx = fmaf(pc, st[r].x, ps * oy);
            float ny = fmaf(pc, st[r].y, -ps * ox);
            if (act) { st[r].x = nx; st[r].y = ny; }
        }
    }
}

// RZ on a reg-bit wire (ancilla)
template <int M>
__device__ __forceinline__ void rz_reg(float2 (&st)[16], float c, float s) {
#pragma unroll
    for (int r = 0; r < 16; ++r) {
        float ss = (r & M) ? s : -s;
        float x = st[r].x, y = st[r].y;
        st[r].x = fmaf(c, x, -ss * y);
        st[r].y = fmaf(c, y, ss * x);
    }
}

__device__ __forceinline__ void cnot_st(float2 (&st)[16]) {
#pragma unroll
    for (int r = 0; r < 16; ++r) {
        if ((r & 3) == 2) { float2 tmp = st[r]; st[r] = st[r | 1]; st[r | 1] = tmp; }
    }
}

__device__ __forceinline__ void pcphase_g(float2 (&st)[16], float cphi, float sphi) {
#pragma unroll
    for (int r = 0; r < 16; ++r) {
        float ss = ((r & 3) == 0) ? sphi : -sphi;
        float x = st[r].x, y = st[r].y;
        st[r].x = fmaf(cphi, x, -ss * y);
        st[r].y = fmaf(cphi, y, ss * x);
    }
}

__device__ __forceinline__ void apply_op(float2 (&st)[16], int lane, int W, int tid,
                                         float* sx, float* sy,
                                         int cw, int tw, float4 c, float4 s) {
    if (cw < 0) {  // RY
        if (tw < 5)       ry_lane(st, 1 << (4 - tw), 4 - tw, lane, c, s);
        else if (tw == 5) wire5_op(st, sx, sy, tid, W, true, true, 0, c, s);
        else if (tw == 6) ry_reg<8>(st, c, s);
        else              ry_reg<4>(st, c, s);
    } else {       // CRX
        bool actBase; int crm = 0;
        if (cw < 5)       actBase = ((lane >> (4 - cw)) & 1) != 0;
        else if (cw == 5) actBase = (W == 1);
        else { actBase = true; crm = (cw == 6) ? 8 : 4; }
        if (tw < 5)       crx_lane(st, 1 << (4 - tw), actBase, crm, c, s);
        else if (tw == 5) wire5_op(st, sx, sy, tid, W, false, actBase, crm, c, s);
        else if (tw == 6) crx_reg<8>(st, actBase, crm, c, s);
        else              crx_reg<4>(st, actBase, crm, c, s);
    }
}

// sim14 with 2 layers, coefficients from float4 tables (2x LDS.128 per step)
__device__ __forceinline__ void run_sim14_2l(float2 (&st)[16], int lane, int W, int tid,
                                             float* sx, float* sy,
                                             const float4* tabc, const float4* tabs,
                                             bool adj) {
    if (!adj) {
#pragma unroll 1
        for (int step = 0; step < 64; ++step) {
            int o = step & 31;
            float4 c = tabc[step];
            float4 s = tabs[step];
            apply_op(st, lane, W, tid, sx, sy, c_OPC[o], c_OPT[o], c, s);
        }
    } else {
#pragma unroll 1
        for (int step = 63; step >= 0; --step) {
            int o = step & 31;
            float4 c = tabc[step];
            float4 s0 = tabs[step];
            float4 s = make_float4(-s0.x, -s0.y, -s0.z, -s0.w);
            apply_op(st, lane, W, tid, sx, sy, c_OPC[o], c_OPT[o], c, s);
        }
    }
}

__device__ __forceinline__ void do_prepare(float2 (&st)[16], const float2* tabp, bool adj) {
    if (!adj) {
#pragma unroll
        for (int ly = 0; ly < 2; ++ly) {
            float2 a  = tabp[ly*4+0]; ry_reg<2>(st, splat4(a.x),  splat4(a.y));
            float2 z  = tabp[ly*4+1]; rz_reg<2>(st, z.x, z.y);
            float2 a2 = tabp[ly*4+2]; ry_reg<1>(st, splat4(a2.x), splat4(a2.y));
            float2 z2 = tabp[ly*4+3]; rz_reg<1>(st, z2.x, z2.y);
            cnot_st(st);
        }
    } else {
#pragma unroll
        for (int ly = 1; ly >= 0; --ly) {
            cnot_st(st);
            float2 z2 = tabp[ly*4+3]; rz_reg<1>(st, z2.x, -z2.y);
            float2 a2 = tabp[ly*4+2]; ry_reg<1>(st, splat4(a2.x), splat4(-a2.y));
            float2 z  = tabp[ly*4+1]; rz_reg<2>(st, z.x, -z.y);
            float2 a  = tabp[ly*4+0]; ry_reg<2>(st, splat4(a.x),  splat4(-a.y));
        }
    }
}

// ---------------- simulate kernel: 2 warps per batch element ----------------
__global__ void __launch_bounds__(64, 1) k_sim(
    const float* __restrict__ prep_p, const float* __restrict__ sig,
    const float* __restrict__ qff,
    const float* __restrict__ A_obs, const float* __restrict__ B_obs,
    const float* __restrict__ D_obs,
    const float* __restrict__ head_w, const float* __restrict__ head_b,
    float* __restrict__ out) {
    __shared__ float sx[1024];      // exchange / obs real
    __shared__ float sy[1024];      // exchange / obs imag
    __shared__ float4 tabc[64];     // cos(th/2) per step, lanes = select s
    __shared__ float4 tabs[64];     // sin(th/2) per step
    __shared__ float2 tabq[32];
    __shared__ float2 tabp[8];
    __shared__ float2 tabsig[4];
    __shared__ float part[14];

    const int tid  = threadIdx.x;
    const int lane = tid & 31;
    const int W    = tid >> 5;
    const int b    = blockIdx.x;
    const float* tsr = g_ts + b * 256;

    if (tid < 64) {
        float c0,s0,c1,s1,c2,s2,c3,s3;
        sincosf(tsr[tid]       * 0.5f, &s0, &c0);
        sincosf(tsr[64 + tid]  * 0.5f, &s1, &c1);
        sincosf(tsr[128 + tid] * 0.5f, &s2, &c2);
        sincosf(tsr[192 + tid] * 0.5f, &s3, &c3);
        tabc[tid] = make_float4(c0, c1, c2, c3);
        tabs[tid] = make_float4(s0, s1, s2, s3);
    }
    if (tid < 32) { float sn, cc; sincosf(qff[tid] * 0.5f, &sn, &cc); tabq[tid] = make_float2(cc, sn); }
    if (tid < 8)  { float sn, cc; sincosf(prep_p[tid] * 0.5f, &sn, &cc); tabp[tid] = make_float2(cc, sn); }
    if (tid < 4)  { float sn, cc; sincosf(sig[tid], &sn, &cc); tabsig[tid] = make_float2(cc, sn); }
    __syncthreads();

    float2 st[16];
#pragma unroll
    for (int r = 0; r < 16; ++r) st[r] = make_float2(0.f, 0.f);
    if (tid == 0) st[0].x = 1.f;

    { float2 p = tabsig[0]; pcphase_g(st, p.x, p.y); }
#pragma unroll 1
    for (int k = 0; k < 3; ++k) {
        do_prepare(st, tabp, false);
        run_sim14_2l(st, lane, W, tid, sx, sy, tabc, tabs, (k & 1) != 0);
        do_prepare(st, tabp, true);
        float2 p = tabsig[k + 1];
        pcphase_g(st, p.x, p.y);
    }
    // final sim14 with qff params, 1 layer
#pragma unroll 1
    for (int step = 0; step < 32; ++step) {
        float2 tq = tabq[step];
        apply_op(st, lane, W, tid, sx, sy, c_OPC[step], c_OPT[step],
                 splat4(tq.x), splat4(tq.y));
    }

    // dump state to shared (swizzled) for expectation values
    __syncthreads();
#pragma unroll
    for (int r = 0; r < 16; ++r) {
        int n = (lane << 5) | (W << 4) | r;
        sx[OIDX(n)] = st[r].x; sy[OIDX(n)] = st[r].y;
    }
    __syncthreads();

#pragma unroll 1
    for (int w = 0; w < 7; ++w) {
        const float* Aw = A_obs + w * 6;
        const float* Bw = B_obs + w * 6;
        const float* Dw = D_obs + w * 4;
        float d0 = 2.f * Dw[1], d1 = 2.f * Dw[2], d2 = 2.f * Dw[3];
        float a10 = Aw[0], b10 = Bw[0], a20 = Aw[1], b20 = Bw[1], a21 = Aw[2], b21 = Bw[2];
        float a30 = Aw[3], b30 = Bw[3], a31 = Aw[4], b31 = Bw[4], a32 = Aw[5], b32 = Bw[5];
        int b1 = 8 - w;
        int m1 = 1 << b1, m0 = m1 << 1;
        int lowmask = m1 - 1;
        float acc = 0.f;
        for (int gi = tid; gi < 256; gi += 64) {
            int n = ((gi & ~lowmask) << 2) | (gi & lowmask);
            int i0 = OIDX(n), i1 = OIDX(n + m1), i2 = OIDX(n + m0), i3 = OIDX(n + m0 + m1);
            float2 v0 = make_float2(sx[i0], sy[i0]);
            float2 v1 = make_float2(sx[i1], sy[i1]);
            float2 v2 = make_float2(sx[i2], sy[i2]);
            float2 v3 = make_float2(sx[i3], sy[i3]);
            acc += d0 * (v0.x * v0.x + v0.y * v0.y);
            acc += d1 * (v1.x * v1.x + v1.y * v1.y);
            acc += d2 * (v2.x * v2.x + v2.y * v2.y);
#define CROSS(vi, vj, aa, bb) { \
            float pr = vi.x * vj.x + vi.y * vj.y; \
            float pim = vi.x * vj.y - vi.y * vj.x; \
            acc += 2.f * (pr * (aa) - pim * (bb)); }
            CROSS(v1, v0, a10, b10)
            CROSS(v2, v0, a20, b20)
            CROSS(v2, v1, a21, b21)
            CROSS(v3, v0, a30, b30)
            CROSS(v3, v1, a31, b31)
            CROSS(v3, v2, a32, b32)
#undef CROSS
        }
#pragma unroll
        for (int off = 16; off; off >>= 1) acc += __shfl_xor_sync(FULLMASK, acc, off);
        if (lane == 0) part[w * 2 + W] = acc;
    }
    __syncthreads();

    // head: out[b][j] = sum_w e[w] * head_w[j*7+w] + head_b[j]
#pragma unroll
    for (int u = 0; u < 2; ++u) {
        int j = u * 64 + tid;
        float o = head_b[j];
#pragma unroll
        for (int w = 0; w < 7; ++w) o = fmaf(part[w*2] + part[w*2+1], head_w[j * 7 + w], o);
        out[b * 128 + j] = o;
    }
}

// ---------------- fused MLP kernel: 2 rows/block, 512 threads, split-K ----------------
__device__ __forceinline__ float silu_f(float x) { return x * (1.f / (1.f + expf(-x))); }

__global__ void __launch_bounds__(512) k_mlp(
    const float* __restrict__ t, const float* __restrict__ z_t,
    const float* __restrict__ te_w1, const float* __restrict__ te_b1,
    const float* __restrict__ te_w2, const float* __restrict__ te_b2,
    const float* __restrict__ ip_w1, const float* __restrict__ ip_b1,
    const float* __restrict__ ip_w2, const float* __restrict__ ip_b2) {
    __shared__ float emb[2][128];
    __shared__ float hb[2][128];
    __shared__ float cat[2][256];
    __shared__ float g1[2][256];
    __shared__ float red[1024];
    const int tid = threadIdx.x;
    const int r0 = blockIdx.x * 2;

    // stage A: sinusoidal embedding + copy z_t into cat
    if (tid < 256) {
        int row = tid >> 7, i = tid & 127;
        float tv = t[r0 + row];
        int ii = i & 63;
        float f = expf(-0.14391156831212787f * (float)ii);
        float a = tv * f;
        emb[row][i] = (i < 64) ? cosf(a) : sinf(a);
        cat[row][i] = z_t[(r0 + row) * 128 + i];
    }
    __syncthreads();

    // stage B compute: 128 outputs x 4 K-chunks of 32
    {
        int j = tid & 127, kc = tid >> 7;
        float a0 = 0.f, a1 = 0.f;
        const float4* w4 = reinterpret_cast<const float4*>(te_w1 + j * 128 + kc * 32);
#pragma unroll
        for (int k4 = 0; k4 < 8; ++k4) {
            float4 wv = w4[k4];
            float4 x0 = *reinterpret_cast<const float4*>(&emb[0][kc * 32 + k4 * 4]);
            float4 x1 = *reinterpret_cast<const float4*>(&emb[1][kc * 32 + k4 * 4]);
            a0 = fmaf(wv.x, x0.x, a0); a0 = fmaf(wv.y, x0.y, a0);
            a0 = fmaf(wv.z, x0.z, a0); a0 = fmaf(wv.w, x0.w, a0);
            a1 = fmaf(wv.x, x1.x, a1); a1 = fmaf(wv.y, x1.y, a1);
            a1 = fmaf(wv.z, x1.z, a1); a1 = fmaf(wv.w, x1.w, a1);
        }
        red[kc * 256 + j * 2 + 0] = a0;
        red[kc * 256 + j * 2 + 1] = a1;
    }
    __syncthreads();
    if (tid < 256) {   // stage B reduce -> hb
        int j = tid >> 1, row = tid & 1;
        float v = te_b1[j] + red[j * 2 + row] + red[256 + j * 2 + row]
                + red[512 + j * 2 + row] + red[768 + j * 2 + row];
        hb[row][j] = silu_f(v);
    }
    __syncthreads();

    // stage C compute: t_emb2 = te_w2 @ h + te_b2
    {
        int j = tid & 127, kc = tid >> 7;
        float a0 = 0.f, a1 = 0.f;
        const float4* w4 = reinterpret_cast<const float4*>(te_w2 + j * 128 + kc * 32);
#pragma unroll
        for (int k4 = 0; k4 < 8; ++k4) {
            float4 wv = w4[k4];
            float4 x0 = *reinterpret_cast<const float4*>(&hb[0][kc * 32 + k4 * 4]);
            float4 x1 = *reinterpret_cast<const float4*>(&hb[1][kc * 32 + k4 * 4]);
            a0 = fmaf(wv.x, x0.x, a0); a0 = fmaf(wv.y, x0.y, a0);
            a0 = fmaf(wv.z, x0.z, a0); a0 = fmaf(wv.w, x0.w, a0);
            a1 = fmaf(wv.x, x1.x, a1); a1 = fmaf(wv.y, x1.y, a1);
            a1 = fmaf(wv.z, x1.z, a1); a1 = fmaf(wv.w, x1.w, a1);
        }
        red[kc * 256 + j * 2 + 0] = a0;
        red[kc * 256 + j * 2 + 1] = a1;
    }
    __syncthreads();
    if (tid < 256) {   // stage C reduce -> cat[., 128+j]
        int j = tid >> 1, row = tid & 1;
        float v = te_b2[j] + red[j * 2 + row] + red[256 + j * 2 + row]
                + red[512 + j * 2 + row] + red[768 + j * 2 + row];
        cat[row][128 + j] = v;
    }
    __syncthreads();

    // stage D compute: 256 outputs x 2 K-halves of 128
    {
        int j = tid & 255, h = tid >> 8;
        float a0 = 0.f, a1 = 0.f;
        const float4* w4 = reinterpret_cast<const float4*>(ip_w1 + j * 256 + h * 128);
#pragma unroll 8
        for (int k4 = 0; k4 < 32; ++k4) {
            float4 wv = w4[k4];
            float4 x0 = *reinterpret_cast<const float4*>(&cat[0][h * 128 + k4 * 4]);
            float4 x1 = *reinterpret_cast<const float4*>(&cat[1][h * 128 + k4 * 4]);
            a0 = fmaf(wv.x, x0.x, a0); a0 = fmaf(wv.y, x0.y, a0);
            a0 = fmaf(wv.z, x0.z, a0); a0 = fmaf(wv.w, x0.w, a0);
            a1 = fmaf(wv.x, x1.x, a1); a1 = fmaf(wv.y, x1.y, a1);
            a1 = fmaf(wv.z, x1.z, a1); a1 = fmaf(wv.w, x1.w, a1);
        }
        red[h * 512 + j * 2 + 0] = a0;
        red[h * 512 + j * 2 + 1] = a1;
    }
    __syncthreads();
    {   // stage D reduce -> g1 (512 threads: 256 j x 2 rows)
        int j = tid >> 1, row = tid & 1;
        float v = ip_b1[j] + red[j * 2 + row] + red[512 + j * 2 + row];
        g1[row][j] = silu_f(v);
    }
    __syncthreads();

    // stage E compute: ts = sigmoid(ip_w2 @ g1 + ip_b2) * 2pi
    {
        int j = tid & 255, h = tid >> 8;
        float a0 = 0.f, a1 = 0.f;
        const float4* w4 = reinterpret_cast<const float4*>(ip_w2 + j * 256 + h * 128);
#pragma unroll 8
        for (int k4 = 0; k4 < 32; ++k4) {
            float4 wv = w4[k4];
            float4 x0 = *reinterpret_cast<const float4*>(&g1[0][h * 128 + k4 * 4]);
            float4 x1 = *reinterpret_cast<const float4*>(&g1[1][h * 128 + k4 * 4]);
            a0 = fmaf(wv.x, x0.x, a0); a0 = fmaf(wv.y, x0.y, a0);
            a0 = fmaf(wv.z, x0.z, a0); a0 = fmaf(wv.w, x0.w, a0);
            a1 = fmaf(wv.x, x1.x, a1); a1 = fmaf(wv.y, x1.y, a1);
            a1 = fmaf(wv.z, x1.z, a1); a1 = fmaf(wv.w, x1.w, a1);
        }
        red[h * 512 + j * 2 + 0] = a0;
        red[h * 512 + j * 2 + 1] = a1;
    }
    __syncthreads();
    {   // stage E reduce -> g_ts
        int j = tid >> 1, row = tid & 1;
        float v = ip_b2[j] + red[j * 2 + row] + red[512 + j * 2 + row];
        g_ts[(r0 + row) * 256 + j] = TWO_PI_F / (1.f + expf(-v));
    }
}

// ---------------- launch ----------------
extern "C" void kernel_launch(void* const* d_in, const int* in_sizes, int n_in,
                              void* d_out, int out_size) {
    const float* z_t    = (const float*)d_in[0];
    const float* t      = (const float*)d_in[1];
    const float* te_w1  = (const float*)d_in[2];
    const float* te_b1  = (const float*)d_in[3];
    const float* te_w2  = (const float*)d_in[4];
    const float* te_b2  = (const float*)d_in[5];
    const float* ip_w1  = (const float*)d_in[6];
    const float* ip_b1  = (const float*)d_in[7];
    const float* ip_w2  = (const float*)d_in[8];
    const float* ip_b2  = (const float*)d_in[9];
    const float* prep   = (const float*)d_in[10];
    const float* sig    = (const float*)d_in[11];
    const float* qff    = (const float*)d_in[12];
    const float* A_obs  = (const float*)d_in[13];
    const float* B_obs  = (const float*)d_in[14];
    const float* D_obs  = (const float*)d_in[15];
    const float* head_w = (const float*)d_in[16];
    const float* head_b = (const float*)d_in[17];
    float* out = (float*)d_out;

    k_mlp<<<128, 512>>>(t, z_t, te_w1, te_b1, te_w2, te_b2, ip_w1, ip_b1, ip_w2, ip_b2);
    k_sim<<<256, 64>>>(prep, sig, qff, A_obs, B_obs, D_obs, head_w, head_b, out);
}

// round 11
// speedup vs baseline: 1.9235x; 1.0676x over previous
#include <cuda_runtime.h>
#include <math.h>

#define FULLMASK 0xffffffffu
#define TWO_PI_F 6.2831853071795864f

// ---------------- scratch ----------------
__device__ float g_ts[256 * 256];   // ts angles, row b: [s*64 + g]

// ---------------- sim14 single-layer op schedule (32 ops) ----------------
__constant__ int c_OPC[32] = {
    -1,-1,-1,-1,-1,-1,-1,-1,
     7, 6, 5, 4, 3, 2, 1, 0,
    -1,-1,-1,-1,-1,-1,-1,-1,
     7, 0, 1, 2, 3, 4, 5, 6};
__constant__ int c_OPT[32] = {
     0, 1, 2, 3, 4, 5, 6, 7,
     0, 7, 6, 5, 4, 3, 2, 1,
     0, 1, 2, 3, 4, 5, 6, 7,
     6, 7, 0, 1, 2, 3, 4, 5};

// ---------------- helpers ----------------
__device__ __forceinline__ float g4(float4 v, int i) {
    return (i == 0) ? v.x : (i == 1) ? v.y : (i == 2) ? v.z : v.w;
}
__device__ __forceinline__ float4 splat4(float v) { return make_float4(v, v, v, v); }

// State layout (4 warps per batch element, 128 threads):
//   flat index n (10 bits): bit9..bit5 = wires 0..4 (lane bits 4..0),
//   bit4 = wire5 (tid bit 6), bit3 = wire6 (tid bit 5),
//   bit2 = wire7 (reg M=4), bit1 = wire8/anc0 (M=2), bit0 = wire9/anc1 (M=1).
//   Each thread holds 8 float2 (r = bits 2..0). select index s = r & 3.
#define OIDX(n) ((n) ^ (((n) >> 5) & 31))

// RY on a lane-bit wire
__device__ __forceinline__ void ry_lane(float2 (&st)[8], int lmask, int lb, int lane,
                                        float4 c, float4 s) {
    float sg = ((lane >> lb) & 1) ? 1.f : -1.f;
    float4 sv = make_float4(g4(s,0)*sg, g4(s,1)*sg, g4(s,2)*sg, g4(s,3)*sg);
#pragma unroll
    for (int r = 0; r < 8; ++r) {
        float ox = __shfl_xor_sync(FULLMASK, st[r].x, lmask);
        float oy = __shfl_xor_sync(FULLMASK, st[r].y, lmask);
        float pc = g4(c, r & 3), ps = g4(sv, r & 3);
        st[r].x = fmaf(pc, st[r].x, ps * ox);
        st[r].y = fmaf(pc, st[r].y, ps * oy);
    }
}

// RY on a reg-bit wire (mask M in {4,2,1})
template <int M>
__device__ __forceinline__ void ry_reg(float2 (&st)[8], float4 c, float4 s) {
#pragma unroll
    for (int r = 0; r < 8; ++r) {
        if ((r & M) == 0) {
            const int r1 = r | M;
            float pc = g4(c, r & 3), ps = g4(s, r & 3);
            float ax = st[r].x, ay = st[r].y, bx = st[r1].x, by = st[r1].y;
            st[r].x = fmaf(pc, ax, -ps * bx);
            st[r].y = fmaf(pc, ay, -ps * by);
            st[r1].x = fmaf(ps, ax, pc * bx);
            st[r1].y = fmaf(ps, ay, pc * by);
        }
    }
}

// CRX with target on a lane-bit wire. act = actBase && (crm==0 || (r&crm))
__device__ __forceinline__ void crx_lane(float2 (&st)[8], int tmask,
                                         bool actBase, int crm,
                                         float4 c, float4 s) {
#pragma unroll
    for (int r = 0; r < 8; ++r) {
        float ox = __shfl_xor_sync(FULLMASK, st[r].x, tmask);
        float oy = __shfl_xor_sync(FULLMASK, st[r].y, tmask);
        bool act = actBase && (crm == 0 || (r & crm) != 0);
        float pc = g4(c, r & 3), ps = g4(s, r & 3);
        float nx = fmaf(pc, st[r].x, ps * oy);
        float ny = fmaf(pc, st[r].y, -ps * ox);
        if (act) { st[r].x = nx; st[r].y = ny; }
    }
}

// CRX with target on a reg-bit wire (mask M)
template <int M>
__device__ __forceinline__ void crx_reg(float2 (&st)[8], bool actBase, int crm,
                                        float4 c, float4 s) {
#pragma unroll
    for (int r = 0; r < 8; ++r) {
        if ((r & M) == 0) {
            const int r1 = r | M;
            bool act = actBase && (crm == 0 || (r & crm) != 0);
            float pc = g4(c, r & 3), ps = g4(s, r & 3);
            float ax = st[r].x, ay = st[r].y, bx = st[r1].x, by = st[r1].y;
            float n0x = fmaf(pc, ax, ps * by);
            float n0y = fmaf(pc, ay, -ps * bx);
            float n1x = fmaf(pc, bx, ps * ay);
            float n1y = fmaf(pc, by, -ps * ax);
            if (act) { st[r] = make_float2(n0x, n0y); st[r1] = make_float2(n1x, n1y); }
        }
    }
}

// Op (RY or CRX) targeting a warp bit: smem exchange. xm = 64 (w5) or 32 (w6)
__device__ __forceinline__ void warp_op(float2 (&st)[8], float* sx, float* sy,
                                        int tid, int xm, bool isRY,
                                        bool actBase, int crm, float4 c, float4 s) {
    __syncthreads();
#pragma unroll
    for (int r = 0; r < 8; ++r) { sx[r * 128 + tid] = st[r].x; sy[r * 128 + tid] = st[r].y; }
    __syncthreads();
    const int p = tid ^ xm;
    const float sg = (tid & xm) ? 1.f : -1.f;
#pragma unroll
    for (int r = 0; r < 8; ++r) {
        float ox = sx[r * 128 + p], oy = sy[r * 128 + p];
        float pc = g4(c, r & 3), ps = g4(s, r & 3);
        if (isRY) {
            float pss = sg * ps;
            st[r].x = fmaf(pc, st[r].x, pss * ox);
            st[r].y = fmaf(pc, st[r].y, pss * oy);
        } else {
            bool act = actBase && (crm == 0 || (r & crm) != 0);
            float nx = fmaf(pc, st[r].x, ps * oy);
            float ny = fmaf(pc, st[r].y, -ps * ox);
            if (act) { st[r].x = nx; st[r].y = ny; }
        }
    }
}

// RZ on a reg-bit wire (ancilla)
template <int M>
__device__ __forceinline__ void rz_reg(float2 (&st)[8], float c, float s) {
#pragma unroll
    for (int r = 0; r < 8; ++r) {
        float ss = (r & M) ? s : -s;
        float x = st[r].x, y = st[r].y;
        st[r].x = fmaf(c, x, -ss * y);
        st[r].y = fmaf(c, y, ss * x);
    }
}

__device__ __forceinline__ void cnot_st(float2 (&st)[8]) {
#pragma unroll
    for (int r = 0; r < 8; ++r) {
        if ((r & 3) == 2) { float2 tmp = st[r]; st[r] = st[r | 1]; st[r | 1] = tmp; }
    }
}

__device__ __forceinline__ void pcphase_g(float2 (&st)[8], float cphi, float sphi) {
#pragma unroll
    for (int r = 0; r < 8; ++r) {
        float ss = ((r & 3) == 0) ? sphi : -sphi;
        float x = st[r].x, y = st[r].y;
        st[r].x = fmaf(cphi, x, -ss * y);
        st[r].y = fmaf(cphi, y, ss * x);
    }
}

__device__ __forceinline__ void apply_op(float2 (&st)[8], int lane, int tid,
                                         float* sx, float* sy,
                                         int cw, int tw, float4 c, float4 s) {
    if (cw < 0) {  // RY
        if (tw < 5)       ry_lane(st, 1 << (4 - tw), 4 - tw, lane, c, s);
        else if (tw == 5) warp_op(st, sx, sy, tid, 64, true, true, 0, c, s);
        else if (tw == 6) warp_op(st, sx, sy, tid, 32, true, true, 0, c, s);
        else              ry_reg<4>(st, c, s);
    } else {       // CRX
        bool actBase; int crm = 0;
        if (cw < 5)       actBase = ((lane >> (4 - cw)) & 1) != 0;
        else if (cw == 5) actBase = ((tid >> 6) & 1) != 0;
        else if (cw == 6) actBase = ((tid >> 5) & 1) != 0;
        else { actBase = true; crm = 4; }
        if (tw < 5)       crx_lane(st, 1 << (4 - tw), actBase, crm, c, s);
        else if (tw == 5) warp_op(st, sx, sy, tid, 64, false, actBase, crm, c, s);
        else if (tw == 6) warp_op(st, sx, sy, tid, 32, false, actBase, crm, c, s);
        else              crx_reg<4>(st, actBase, crm, c, s);
    }
}

// sim14 with 2 layers (compact loop, runtime dispatch)
__device__ __forceinline__ void run_sim14_2l(float2 (&st)[8], int lane, int tid,
                                             float* sx, float* sy,
                                             const float4* tabc, const float4* tabs,
                                             bool adj) {
    if (!adj) {
#pragma unroll 1
        for (int step = 0; step < 64; ++step) {
            int o = step & 31;
            float4 c = tabc[step];
            float4 s = tabs[step];
            apply_op(st, lane, tid, sx, sy, c_OPC[o], c_OPT[o], c, s);
        }
    } else {
#pragma unroll 1
        for (int step = 63; step >= 0; --step) {
            int o = step & 31;
            float4 c = tabc[step];
            float4 s0 = tabs[step];
            float4 s = make_float4(-s0.x, -s0.y, -s0.z, -s0.w);
            apply_op(st, lane, tid, sx, sy, c_OPC[o], c_OPT[o], c, s);
        }
    }
}

__device__ __forceinline__ void do_prepare(float2 (&st)[8], const float2* tabp, bool adj) {
    if (!adj) {
#pragma unroll
        for (int ly = 0; ly < 2; ++ly) {
            float2 a  = tabp[ly*4+0]; ry_reg<2>(st, splat4(a.x),  splat4(a.y));
            float2 z  = tabp[ly*4+1]; rz_reg<2>(st, z.x, z.y);
            float2 a2 = tabp[ly*4+2]; ry_reg<1>(st, splat4(a2.x), splat4(a2.y));
            float2 z2 = tabp[ly*4+3]; rz_reg<1>(st, z2.x, z2.y);
            cnot_st(st);
        }
    } else {
#pragma unroll
        for (int ly = 1; ly >= 0; --ly) {
            cnot_st(st);
            float2 z2 = tabp[ly*4+3]; rz_reg<1>(st, z2.x, -z2.y);
            float2 a2 = tabp[ly*4+2]; ry_reg<1>(st, splat4(a2.x), splat4(-a2.y));
            float2 z  = tabp[ly*4+1]; rz_reg<2>(st, z.x, -z.y);
            float2 a  = tabp[ly*4+0]; ry_reg<2>(st, splat4(a.x),  splat4(-a.y));
        }
    }
}

// ---------------- simulate kernel: 4 warps per batch element ----------------
__global__ void __launch_bounds__(128) k_sim(
    const float* __restrict__ prep_p, const float* __restrict__ sig,
    const float* __restrict__ qff,
    const float* __restrict__ A_obs, const float* __restrict__ B_obs,
    const float* __restrict__ D_obs,
    const float* __restrict__ head_w, const float* __restrict__ head_b,
    float* __restrict__ out) {
    __shared__ float sx[1024];      // exchange / obs real (8r x 128tid)
    __shared__ float sy[1024];      // exchange / obs imag
    __shared__ float4 tabc[64];
    __shared__ float4 tabs[64];
    __shared__ float2 tabq[32];
    __shared__ float2 tabp[8];
    __shared__ float2 tabsig[4];
    __shared__ float part[28];

    const int tid  = threadIdx.x;
    const int lane = tid & 31;
    const int warp = tid >> 5;
    const int b    = blockIdx.x;
    const float* tsr = g_ts + b * 256;

    if (tid < 64) {
        float c0,s0,c1,s1,c2,s2,c3,s3;
        sincosf(tsr[tid]       * 0.5f, &s0, &c0);
        sincosf(tsr[64 + tid]  * 0.5f, &s1, &c1);
        sincosf(tsr[128 + tid] * 0.5f, &s2, &c2);
        sincosf(tsr[192 + tid] * 0.5f, &s3, &c3);
        tabc[tid] = make_float4(c0, c1, c2, c3);
        tabs[tid] = make_float4(s0, s1, s2, s3);
    } else if (tid < 96) {
        int q = tid - 64;
        float sn, cc; sincosf(qff[q] * 0.5f, &sn, &cc);
        tabq[q] = make_float2(cc, sn);
    } else if (tid < 104) {
        int q = tid - 96;
        float sn, cc; sincosf(prep_p[q] * 0.5f, &sn, &cc);
        tabp[q] = make_float2(cc, sn);
    } else if (tid < 108) {
        int q = tid - 104;
        float sn, cc; sincosf(sig[q], &sn, &cc);
        tabsig[q] = make_float2(cc, sn);
    }
    __syncthreads();

    float2 st[8];
#pragma unroll
    for (int r = 0; r < 8; ++r) st[r] = make_float2(0.f, 0.f);
    if (tid == 0) st[0].x = 1.f;

    { float2 p = tabsig[0]; pcphase_g(st, p.x, p.y); }
#pragma unroll 1
    for (int k = 0; k < 3; ++k) {
        do_prepare(st, tabp, false);
        run_sim14_2l(st, lane, tid, sx, sy, tabc, tabs, (k & 1) != 0);
        do_prepare(st, tabp, true);
        float2 p = tabsig[k + 1];
        pcphase_g(st, p.x, p.y);
    }
    // final sim14 with qff params, 1 layer (uniform theta)
#pragma unroll 1
    for (int step = 0; step < 32; ++step) {
        float2 tq = tabq[step];
        apply_op(st, lane, tid, sx, sy, c_OPC[step], c_OPT[step],
                 splat4(tq.x), splat4(tq.y));
    }

    // dump state to shared (swizzled) for expectation values
    __syncthreads();
#pragma unroll
    for (int r = 0; r < 8; ++r) {
        int n = (lane << 5) | (warp << 3) | r;
        int i = OIDX(n);
        sx[i] = st[r].x; sy[i] = st[r].y;
    }
    __syncthreads();

#pragma unroll 1
    for (int w = 0; w < 7; ++w) {
        const float* Aw = A_obs + w * 6;
        const float* Bw = B_obs + w * 6;
        const float* Dw = D_obs + w * 4;
        float d0 = 2.f * Dw[1], d1 = 2.f * Dw[2], d2 = 2.f * Dw[3];
        float a10 = Aw[0], b10 = Bw[0], a20 = Aw[1], b20 = Bw[1], a21 = Aw[2], b21 = Bw[2];
        float a30 = Aw[3], b30 = Bw[3], a31 = Aw[4], b31 = Bw[4], a32 = Aw[5], b32 = Bw[5];
        int b1 = 8 - w;
        int m1 = 1 << b1, m0 = m1 << 1;
        int lowmask = m1 - 1;
        float acc = 0.f;
#pragma unroll
        for (int it = 0; it < 2; ++it) {
            int gi = tid + it * 128;
            int n = ((gi & ~lowmask) << 2) | (gi & lowmask);
            int i0 = OIDX(n), i1 = OIDX(n + m1), i2 = OIDX(n + m0), i3 = OIDX(n + m0 + m1);
            float2 v0 = make_float2(sx[i0], sy[i0]);
            float2 v1 = make_float2(sx[i1], sy[i1]);
            float2 v2 = make_float2(sx[i2], sy[i2]);
            float2 v3 = make_float2(sx[i3], sy[i3]);
            acc += d0 * (v0.x * v0.x + v0.y * v0.y);
            acc += d1 * (v1.x * v1.x + v1.y * v1.y);
            acc += d2 * (v2.x * v2.x + v2.y * v2.y);
#define CROSS(vi, vj, aa, bb) { \
            float pr = vi.x * vj.x + vi.y * vj.y; \
            float pim = vi.x * vj.y - vi.y * vj.x; \
            acc += 2.f * (pr * (aa) - pim * (bb)); }
            CROSS(v1, v0, a10, b10)
            CROSS(v2, v0, a20, b20)
            CROSS(v2, v1, a21, b21)
            CROSS(v3, v0, a30, b30)
            CROSS(v3, v1, a31, b31)
            CROSS(v3, v2, a32, b32)
#undef CROSS
        }
#pragma unroll
        for (int off = 16; off; off >>= 1) acc += __shfl_xor_sync(FULLMASK, acc, off);
        if (lane == 0) part[w * 4 + warp] = acc;
    }
    __syncthreads();

    // head: out[b][j] = sum_w e[w] * head_w[j*7+w] + head_b[j]
    {
        int j = tid;
        float o = head_b[j];
#pragma unroll
        for (int w = 0; w < 7; ++w) {
            float e = part[w*4] + part[w*4+1] + part[w*4+2] + part[w*4+3];
            o = fmaf(e, head_w[j * 7 + w], o);
        }
        out[b * 128 + j] = o;
    }
}

// ---------------- fused MLP kernel: 2 batch rows per block (round-2 exact) ----------------
__device__ __forceinline__ float silu_f(float x) { return x * (1.f / (1.f + expf(-x))); }

__global__ void __launch_bounds__(256) k_mlp(
    const float* __restrict__ t, const float* __restrict__ z_t,
    const float* __restrict__ te_w1, const float* __restrict__ te_b1,
    const float* __restrict__ te_w2, const float* __restrict__ te_b2,
    const float* __restrict__ ip_w1, const float* __restrict__ ip_b1,
    const float* __restrict__ ip_w2, const float* __restrict__ ip_b2) {
    __shared__ float emb[2][128];
    __shared__ float hb[2][128];
    __shared__ float cat[2][256];
    __shared__ float g1[2][256];
    const int tid = threadIdx.x;
    const int r0 = blockIdx.x * 2;

    // stage A: sinusoidal embedding + copy z_t into cat
    {
        int row = tid >> 7, i = tid & 127;
        float tv = t[r0 + row];
        int ii = i & 63;
        float f = expf(-0.14391156831212787f * (float)ii);
        float a = tv * f;
        emb[row][i] = (i < 64) ? cosf(a) : sinf(a);
        cat[row][i] = z_t[(r0 + row) * 128 + i];
    }
    __syncthreads();

    // stage B: h = silu(te_w1 @ emb + te_b1)
    if (tid < 128) {
        int j = tid;
        float a0 = te_b1[j], a1 = a0;
        const float4* w4 = reinterpret_cast<const float4*>(te_w1 + j * 128);
#pragma unroll 8
        for (int k4 = 0; k4 < 32; ++k4) {
            float4 wv = w4[k4];
            float4 x0 = *reinterpret_cast<const float4*>(&emb[0][k4 * 4]);
            float4 x1 = *reinterpret_cast<const float4*>(&emb[1][k4 * 4]);
            a0 = fmaf(wv.x, x0.x, a0); a0 = fmaf(wv.y, x0.y, a0);
            a0 = fmaf(wv.z, x0.z, a0); a0 = fmaf(wv.w, x0.w, a0);
            a1 = fmaf(wv.x, x1.x, a1); a1 = fmaf(wv.y, x1.y, a1);
            a1 = fmaf(wv.z, x1.z, a1); a1 = fmaf(wv.w, x1.w, a1);
        }
        hb[0][j] = silu_f(a0); hb[1][j] = silu_f(a1);
    }
    __syncthreads();

    // stage C: t_emb2 = te_w2 @ h + te_b2 -> cat[., 128+j]
    if (tid < 128) {
        int j = tid;
        float a0 = te_b2[j], a1 = a0;
        const float4* w4 = reinterpret_cast<const float4*>(te_w2 + j * 128);
#pragma unroll 8
        for (int k4 = 0; k4 < 32; ++k4) {
            float4 wv = w4[k4];
            float4 x0 = *reinterpret_cast<const float4*>(&hb[0][k4 * 4]);
            float4 x1 = *reinterpret_cast<const float4*>(&hb[1][k4 * 4]);
            a0 = fmaf(wv.x, x0.x, a0); a0 = fmaf(wv.y, x0.y, a0);
            a0 = fmaf(wv.z, x0.z, a0); a0 = fmaf(wv.w, x0.w, a0);
            a1 = fmaf(wv.x, x1.x, a1); a1 = fmaf(wv.y, x1.y, a1);
            a1 = fmaf(wv.z, x1.z, a1); a1 = fmaf(wv.w, x1.w, a1);
        }
        cat[0][128 + j] = a0; cat[1][128 + j] = a1;
    }
    __syncthreads();

    // stage D: g1 = silu(ip_w1 @ cat + ip_b1)
    {
        int j = tid;
        float a0 = ip_b1[j], a1 = a0;
        const float4* w4 = reinterpret_cast<const float4*>(ip_w1 + j * 256);
#pragma unroll 8
        for (int k4 = 0; k4 < 64; ++k4) {
            float4 wv = w4[k4];
            float4 x0 = *reinterpret_cast<const float4*>(&cat[0][k4 * 4]);
            float4 x1 = *reinterpret_cast<const float4*>(&cat[1][k4 * 4]);
            a0 = fmaf(wv.x, x0.x, a0); a0 = fmaf(wv.y, x0.y, a0);
            a0 = fmaf(wv.z, x0.z, a0); a0 = fmaf(wv.w, x0.w, a0);
            a1 = fmaf(wv.x, x1.x, a1); a1 = fmaf(wv.y, x1.y, a1);
            a1 = fmaf(wv.z, x1.z, a1); a1 = fmaf(wv.w, x1.w, a1);
        }
        g1[0][j] = silu_f(a0); g1[1][j] = silu_f(a1);
    }
    __syncthreads();

    // stage E: ts = sigmoid(ip_w2 @ g1 + ip_b2) * 2pi
    {
        int j = tid;
        float a0 = ip_b2[j], a1 = a0;
        const float4* w4 = reinterpret_cast<const float4*>(ip_w2 + j * 256);
#pragma unroll 8
        for (int k4 = 0; k4 < 64; ++k4) {
            float4 wv = w4[k4];
            float4 x0 = *reinterpret_cast<const float4*>(&g1[0][k4 * 4]);
            float4 x1 = *reinterpret_cast<const float4*>(&g1[1][k4 * 4]);
            a0 = fmaf(wv.x, x0.x, a0); a0 = fmaf(wv.y, x0.y, a0);
            a0 = fmaf(wv.z, x0.z, a0); a0 = fmaf(wv.w, x0.w, a0);
            a1 = fmaf(wv.x, x1.x, a1); a1 = fmaf(wv.y, x1.y, a1);
            a1 = fmaf(wv.z, x1.z, a1); a1 = fmaf(wv.w, x1.w, a1);
        }
        g_ts[r0 * 256 + j]       = TWO_PI_F / (1.f + expf(-a0));
        g_ts[(r0 + 1) * 256 + j] = TWO_PI_F / (1.f + expf(-a1));
    }
}

// ---------------- launch ----------------
extern "C" void kernel_launch(void* const* d_in, const int* in_sizes, int n_in,
                              void* d_out, int out_size) {
    const float* z_t    = (const float*)d_in[0];
    const float* t      = (const float*)d_in[1];
    const float* te_w1  = (const float*)d_in[2];
    const float* te_b1  = (const float*)d_in[3];
    const float* te_w2  = (const float*)d_in[4];
    const float* te_b2  = (const float*)d_in[5];
    const float* ip_w1  = (const float*)d_in[6];
    const float* ip_b1  = (const float*)d_in[7];
    const float* ip_w2  = (const float*)d_in[8];
    const float* ip_b2  = (const float*)d_in[9];
    const float* prep   = (const float*)d_in[10];
    const float* sig    = (const float*)d_in[11];
    const float* qff    = (const float*)d_in[12];
    const float* A_obs  = (const float*)d_in[13];
    const float* B_obs  = (const float*)d_in[14];
    const float* D_obs  = (const float*)d_in[15];
    const float* head_w = (const float*)d_in[16];
    const float* head_b = (const float*)d_in[17];
    float* out = (float*)d_out;

    k_mlp<<<128, 256>>>(t, z_t, te_w1, te_b1, te_w2, te_b2, ip_w1, ip_b1, ip_w2, ip_b2);
    k_sim<<<256, 128>>>(prep, sig, qff, A_obs, B_obs, D_obs, head_w, head_b, out);
}